// round 5
// baseline (speedup 1.0000x reference)
#include <cuda_runtime.h>
#include <cuda_bf16.h>
#include <mma.h>
#include <math.h>

using namespace nvcuda;

#define SEQ   4096
#define BATCH 8
#define MD    4
#define ORDER 256
#define INPUT 256
#define HID   512
#define MSZ   1280
#define NH    4096      // complex FFT size (= 8192/2), real-FFT packing
#define LOGH  12
#define KS    4160      // spectrum row stride: 4096 bitrev slots + nyquist + pad
#define FFT_T 512

typedef wmma::fragment<wmma::matrix_a, 16, 16, 16, __nv_bfloat16, wmma::row_major> FA;
typedef wmma::fragment<wmma::matrix_b, 16, 16, 16, __nv_bfloat16, wmma::row_major> FBr;
typedef wmma::fragment<wmma::matrix_b, 16, 16, 16, __nv_bfloat16, wmma::col_major> FBc;
typedef wmma::fragment<wmma::accumulator, 16, 16, 16, float> FC;

// ---------------- scratch (static device globals; no allocation) ----------------
__device__ float  g_u  [32 * SEQ];
__device__ float2 g_tw [NH];            // e^{-2*pi*i*k/8192}
__device__ float  g_Ure[32 * KS];
__device__ float  g_Uim[32 * KS];
__device__ float  g_Hre[ORDER * KS];
__device__ float  g_Him[ORDER * KS];
__device__ float  g_Gre[HID * MD * KS];
__device__ float  g_Gim[HID * MD * KS];
__device__ float  g_hx [BATCH * HID * SEQ];  // x-part of h (pre-relu), [b][h][t]
__device__ float  g_m  [BATCH * HID * SEQ];  // memory-part of h, [b][h][t]

__device__ __forceinline__ int rev12(int x) { return (int)(__brev((unsigned)x) >> 20); }

__device__ __forceinline__ void bsplit(float v, __nv_bfloat16& hi, __nv_bfloat16& lo) {
    hi = __float2bfloat16(v);
    lo = __float2bfloat16(v - __bfloat162float(hi));
}

// ---------------- twiddle table --------------------------------------------------
__global__ void twiddle_kernel() {
    int k = blockIdx.x * blockDim.x + threadIdx.x;
    if (k < NH) {
        float s, c;
        sincospif(-(float)k / 4096.0f, &s, &c);
        g_tw[k] = make_float2(c, s);
    }
}

// ---------------- u = relu(x @ Wu^T + b) ------------------------------------------
__global__ void u_kernel(const float* __restrict__ x,
                         const float* __restrict__ Wu_w,
                         const float* __restrict__ Wu_b) {
    int gw   = (blockIdx.x * blockDim.x + threadIdx.x) >> 5;
    int lane = threadIdx.x & 31;
    if (gw >= BATCH * SEQ) return;
    int b = gw >> 12, t = gw & (SEQ - 1);
    const float* xp = x + (size_t)(b * SEQ + t) * INPUT;
    float a0 = 0.f, a1 = 0.f, a2 = 0.f, a3 = 0.f;
    #pragma unroll
    for (int i = lane; i < INPUT; i += 32) {
        float xv = xp[i];
        a0 = fmaf(xv, __ldg(&Wu_w[0 * INPUT + i]), a0);
        a1 = fmaf(xv, __ldg(&Wu_w[1 * INPUT + i]), a1);
        a2 = fmaf(xv, __ldg(&Wu_w[2 * INPUT + i]), a2);
        a3 = fmaf(xv, __ldg(&Wu_w[3 * INPUT + i]), a3);
    }
    #pragma unroll
    for (int off = 16; off; off >>= 1) {
        a0 += __shfl_down_sync(0xffffffffu, a0, off);
        a1 += __shfl_down_sync(0xffffffffu, a1, off);
        a2 += __shfl_down_sync(0xffffffffu, a2, off);
        a3 += __shfl_down_sync(0xffffffffu, a3, off);
    }
    if (lane == 0) {
        g_u[(b * 4 + 0) * SEQ + t] = fmaxf(a0 + Wu_b[0], 0.f);
        g_u[(b * 4 + 1) * SEQ + t] = fmaxf(a1 + Wu_b[1], 0.f);
        g_u[(b * 4 + 2) * SEQ + t] = fmaxf(a2 + Wu_b[2], 0.f);
        g_u[(b * 4 + 3) * SEQ + t] = fmaxf(a3 + Wu_b[3], 0.f);
    }
}

// ---------------- forward real FFT (radix-2^2 DIF, half spectrum, bitrev slots) ---
__global__ void fft_fwd_kernel(const float* __restrict__ Hin, int mode) {
    __shared__ float sre[NH];
    __shared__ float sim[NH];
    int row = blockIdx.x;
    int tid = threadIdx.x;
    const float* in = mode ? (Hin + (size_t)row * SEQ) : (g_u + (size_t)row * SEQ);
    float* outre = mode ? (g_Hre + (size_t)row * KS) : (g_Ure + (size_t)row * KS);
    float* outim = mode ? (g_Him + (size_t)row * KS) : (g_Uim + (size_t)row * KS);

    const float2* in2 = (const float2*)in;
    #pragma unroll
    for (int r = 0; r < NH / FFT_T; ++r) {
        int n = tid + r * FFT_T;
        if (n < SEQ / 2) { float2 v = in2[n]; sre[n] = v.x; sim[n] = v.y; }
        else             { sre[n] = 0.f;      sim[n] = 0.f; }
    }
    __syncthreads();

    // fused DIF stage pairs (s+1, s), s = LOGH-2 .. 0
    #pragma unroll
    for (int s = LOGH - 2; s >= 0; s -= 2) {
        int m = 1 << s;
        #pragma unroll
        for (int r = 0; r < (NH / 4) / FFT_T; ++r) {
            int k = tid + r * FFT_T;
            int j = k & (m - 1);
            int base = ((k >> s) << (s + 2)) + j;
            int ia = base, ib = base + m, ic = base + 2 * m, id = base + 3 * m;
            float2 w2 = g_tw[j << (LOGH - s - 1)];
            float2 w1 = g_tw[j << (LOGH - s)];
            float ar = sre[ia], ai = sim[ia];
            float br = sre[ib], bi = sim[ib];
            float cr = sre[ic], ci = sim[ic];
            float dr = sre[id], di = sim[id];
            // stage s+1: (a,c) w2 ; (b,d) w2*(-i)
            float a1r = ar + cr, a1i = ai + ci;
            float tr  = ar - cr, ti  = ai - ci;
            float c1r = tr * w2.x - ti * w2.y;
            float c1i = tr * w2.y + ti * w2.x;
            float b1r = br + dr, b1i = bi + di;
            tr = br - dr; ti = bi - di;
            float er = tr * w2.x - ti * w2.y;
            float ei = tr * w2.y + ti * w2.x;
            float d1r = ei, d1i = -er;                     // * (-i)
            // stage s: (a1,b1) and (c1,d1), twiddle w1
            sre[ia] = a1r + b1r;  sim[ia] = a1i + b1i;
            tr = a1r - b1r; ti = a1i - b1i;
            sre[ib] = tr * w1.x - ti * w1.y;
            sim[ib] = tr * w1.y + ti * w1.x;
            sre[ic] = c1r + d1r;  sim[ic] = c1i + d1i;
            tr = c1r - d1r; ti = c1i - d1i;
            sre[id] = tr * w1.x - ti * w1.y;
            sim[id] = tr * w1.y + ti * w1.x;
        }
        __syncthreads();
    }

    #pragma unroll
    for (int r = 0; r < NH / FFT_T; ++r) {
        int j = tid + r * FFT_T;
        if (j == 0) {
            float zr = sre[0], zi = sim[0];
            outre[0]  = zr + zi;  outim[0]  = 0.f;
            outre[NH] = zr - zi;  outim[NH] = 0.f;
        } else {
            int k = rev12(j);
            int p = rev12(NH - k);
            float zjr = sre[j], zji = sim[j];
            float zpr = sre[p], zpi = sim[p];
            float Ar = 0.5f * (zjr + zpr), Ai = 0.5f * (zji - zpi);
            float Br = 0.5f * (zji + zpi), Bi = -0.5f * (zjr - zpr);
            float2 w = g_tw[k];
            outre[j] = Ar + w.x * Br - w.y * Bi;
            outim[j] = Ai + w.x * Bi + w.y * Br;
        }
    }
}

// ---------------- G[h,d,:] = sum_o Wh[h, d*256+o] * Hspec[o,:]  (bf16 split) ------
__global__ __launch_bounds__(256)
void gbuild_bf16_kernel(const float* __restrict__ Wh_w) {
    __shared__ __nv_bfloat16 sAhi[64][40], sAlo[64][40];        // [m][k]
    __shared__ __nv_bfloat16 sBhi[2][32][72], sBlo[2][32][72];  // [re/im][k][n]
    int d  = blockIdx.z;
    int h0 = blockIdx.y * 64;
    int k0 = blockIdx.x * 64;
    int tid = threadIdx.x;
    int w  = tid >> 5;
    int wm = w & 3;
    int wn = w >> 2;

    FC accr[2], acci[2];
    #pragma unroll
    for (int j = 0; j < 2; ++j) { wmma::fill_fragment(accr[j], 0.f); wmma::fill_fragment(acci[j], 0.f); }

    float rA[8], rBr[8], rBi[8];
    // prologue load (o0 = 0)
    #pragma unroll
    for (int r = 0; r < 8; ++r) {
        int e = tid + r * 256;
        rA[r] = Wh_w[(size_t)(h0 + (e >> 5)) * MSZ + d * ORDER + (e & 31)];
        int oo = e >> 6, nn = e & 63;
        size_t src = (size_t)oo * KS + k0 + nn;
        rBr[r] = g_Hre[src];
        rBi[r] = g_Him[src];
    }

    for (int o0 = 0; o0 < ORDER; o0 += 32) {
        #pragma unroll
        for (int r = 0; r < 8; ++r) {
            int e = tid + r * 256;
            bsplit(rA[r], sAhi[e >> 5][e & 31], sAlo[e >> 5][e & 31]);
            int oo = e >> 6, nn = e & 63;
            bsplit(rBr[r], sBhi[0][oo][nn], sBlo[0][oo][nn]);
            bsplit(rBi[r], sBhi[1][oo][nn], sBlo[1][oo][nn]);
        }
        __syncthreads();
        if (o0 + 32 < ORDER) {
            #pragma unroll
            for (int r = 0; r < 8; ++r) {
                int e = tid + r * 256;
                rA[r] = Wh_w[(size_t)(h0 + (e >> 5)) * MSZ + d * ORDER + o0 + 32 + (e & 31)];
                int oo = e >> 6, nn = e & 63;
                size_t src = (size_t)(o0 + 32 + oo) * KS + k0 + nn;
                rBr[r] = g_Hre[src];
                rBi[r] = g_Him[src];
            }
        }
        #pragma unroll
        for (int kk = 0; kk < 32; kk += 16) {
            FA ahi, alo;
            wmma::load_matrix_sync(ahi, &sAhi[wm * 16][kk], 40);
            wmma::load_matrix_sync(alo, &sAlo[wm * 16][kk], 40);
            #pragma unroll
            for (int j = 0; j < 2; ++j) {
                FBr bhi, blo;
                wmma::load_matrix_sync(bhi, &sBhi[0][kk][wn * 32 + j * 16], 72);
                wmma::load_matrix_sync(blo, &sBlo[0][kk][wn * 32 + j * 16], 72);
                wmma::mma_sync(accr[j], ahi, bhi, accr[j]);
                wmma::mma_sync(accr[j], alo, bhi, accr[j]);
                wmma::mma_sync(accr[j], ahi, blo, accr[j]);
                wmma::load_matrix_sync(bhi, &sBhi[1][kk][wn * 32 + j * 16], 72);
                wmma::load_matrix_sync(blo, &sBlo[1][kk][wn * 32 + j * 16], 72);
                wmma::mma_sync(acci[j], ahi, bhi, acci[j]);
                wmma::mma_sync(acci[j], alo, bhi, acci[j]);
                wmma::mma_sync(acci[j], ahi, blo, acci[j]);
            }
        }
        __syncthreads();
    }
    #pragma unroll
    for (int j = 0; j < 2; ++j) {
        size_t dst = ((size_t)(h0 + wm * 16) * MD + d) * KS + k0 + wn * 32 + j * 16;
        wmma::store_matrix_sync(&g_Gre[dst], accr[j], MD * KS, wmma::mem_row_major);
        wmma::store_matrix_sync(&g_Gim[dst], acci[j], MD * KS, wmma::mem_row_major);
    }
}

// ---------------- hx[b,h,t] = sum_i Wh[h,1024+i]*x[b,t,i] + Wh_b[h]  (bf16) -------
__global__ __launch_bounds__(256)
void hx_bf16_kernel(const float* __restrict__ x,
                    const float* __restrict__ Wh_w,
                    const float* __restrict__ Wh_b) {
    __shared__ __nv_bfloat16 sAhi[64][40], sAlo[64][40];    // [h][i]
    __shared__ __nv_bfloat16 sBhi[128][40], sBlo[128][40];  // [t][i]
    __shared__ float sBias[64][16];
    int b  = blockIdx.z;
    int h0 = blockIdx.y * 64;
    int t0 = blockIdx.x * 128;
    int tid = threadIdx.x;
    int w  = tid >> 5;
    int wm = w & 3;
    int wn = w >> 2;

    #pragma unroll
    for (int r = 0; r < 4; ++r) {
        int e = tid + r * 256;
        sBias[e >> 4][e & 15] = Wh_b[h0 + (e >> 4)];
    }
    __syncthreads();

    FC acc[4];
    #pragma unroll
    for (int j = 0; j < 4; ++j)
        wmma::load_matrix_sync(acc[j], &sBias[wm * 16][0], 16, wmma::mem_row_major);

    const float4* x4 = (const float4*)(x + (size_t)(b * SEQ + t0) * INPUT);
    float rA[8];
    float4 rB[4];
    #pragma unroll
    for (int r = 0; r < 8; ++r) {
        int e = tid + r * 256;
        rA[r] = Wh_w[(size_t)(h0 + (e >> 5)) * MSZ + MD * ORDER + (e & 31)];
    }
    #pragma unroll
    for (int r = 0; r < 4; ++r) {
        int e = tid + r * 256;
        rB[r] = x4[(size_t)(e >> 3) * (INPUT / 4) + (e & 7)];
    }

    for (int i0 = 0; i0 < INPUT; i0 += 32) {
        #pragma unroll
        for (int r = 0; r < 8; ++r) {
            int e = tid + r * 256;
            bsplit(rA[r], sAhi[e >> 5][e & 31], sAlo[e >> 5][e & 31]);
        }
        #pragma unroll
        for (int r = 0; r < 4; ++r) {
            int e = tid + r * 256;
            int tt = e >> 3, q = e & 7;
            bsplit(rB[r].x, sBhi[tt][q * 4 + 0], sBlo[tt][q * 4 + 0]);
            bsplit(rB[r].y, sBhi[tt][q * 4 + 1], sBlo[tt][q * 4 + 1]);
            bsplit(rB[r].z, sBhi[tt][q * 4 + 2], sBlo[tt][q * 4 + 2]);
            bsplit(rB[r].w, sBhi[tt][q * 4 + 3], sBlo[tt][q * 4 + 3]);
        }
        __syncthreads();
        if (i0 + 32 < INPUT) {
            #pragma unroll
            for (int r = 0; r < 8; ++r) {
                int e = tid + r * 256;
                rA[r] = Wh_w[(size_t)(h0 + (e >> 5)) * MSZ + MD * ORDER + i0 + 32 + (e & 31)];
            }
            #pragma unroll
            for (int r = 0; r < 4; ++r) {
                int e = tid + r * 256;
                rB[r] = x4[(size_t)(e >> 3) * (INPUT / 4) + ((i0 + 32) >> 2) + (e & 7)];
            }
        }
        #pragma unroll
        for (int kk = 0; kk < 32; kk += 16) {
            FA ahi, alo;
            wmma::load_matrix_sync(ahi, &sAhi[wm * 16][kk], 40);
            wmma::load_matrix_sync(alo, &sAlo[wm * 16][kk], 40);
            #pragma unroll
            for (int j = 0; j < 4; ++j) {
                FBc bhi, blo;
                wmma::load_matrix_sync(bhi, &sBhi[wn * 64 + j * 16][kk], 40);
                wmma::load_matrix_sync(blo, &sBlo[wn * 64 + j * 16][kk], 40);
                wmma::mma_sync(acc[j], ahi, bhi, acc[j]);
                wmma::mma_sync(acc[j], alo, bhi, acc[j]);
                wmma::mma_sync(acc[j], ahi, blo, acc[j]);
            }
        }
        __syncthreads();
    }
    #pragma unroll
    for (int j = 0; j < 4; ++j) {
        size_t dst = ((size_t)b * HID + h0 + wm * 16) * SEQ + t0 + wn * 64 + j * 16;
        wmma::store_matrix_sync(&g_hx[dst], acc[j], SEQ, wmma::mem_row_major);
    }
}

// ---------------- P = sum_d G*U ; real-iFFT (radix-2^2, 2 batches/block) ----------
__global__ __launch_bounds__(FFT_T)
void pifft_kernel() {
    __shared__ float sre[2][NH];
    __shared__ float sim[2][NH];
    __shared__ float s_nyq[2];
    int h  = blockIdx.x >> 2;
    int bp = blockIdx.x & 3;
    int b0 = bp * 2;
    int tid = threadIdx.x;

    const float* Ur0 = g_Ure + (size_t)b0 * MD * KS;
    const float* Ui0 = g_Uim + (size_t)b0 * MD * KS;
    const float* Ur1 = Ur0 + MD * KS;
    const float* Ui1 = Ui0 + MD * KS;
    const float* Gr  = g_Gre + (size_t)h * MD * KS;
    const float* Gi  = g_Gim + (size_t)h * MD * KS;

    #pragma unroll
    for (int r = 0; r < NH / FFT_T; ++r) {
        int j = tid + r * FFT_T;
        float pr0 = 0.f, pi0 = 0.f, pr1 = 0.f, pi1 = 0.f;
        #pragma unroll
        for (int d = 0; d < MD; ++d) {
            float gr = Gr[d * KS + j], gi = Gi[d * KS + j];
            float ur = Ur0[d * KS + j], ui = Ui0[d * KS + j];
            pr0 += ur * gr - ui * gi;
            pi0 += ur * gi + ui * gr;
            ur = Ur1[d * KS + j]; ui = Ui1[d * KS + j];
            pr1 += ur * gr - ui * gi;
            pi1 += ur * gi + ui * gr;
        }
        sre[0][j] = pr0; sim[0][j] = pi0;
        sre[1][j] = pr1; sim[1][j] = pi1;
    }
    if (tid < 2) {
        const float* Urb = tid ? Ur1 : Ur0;
        const float* Uib = tid ? Ui1 : Ui0;
        float pn = 0.f;
        #pragma unroll
        for (int d = 0; d < MD; ++d)
            pn += Urb[d * KS + NH] * Gr[d * KS + NH] - Uib[d * KS + NH] * Gi[d * KS + NH];
        s_nyq[tid] = pn;
    }
    __syncthreads();

    // inverse untangle pack (bit-reversed slots)
    float zr[2][NH / FFT_T], zi[2][NH / FFT_T];
    #pragma unroll
    for (int r = 0; r < NH / FFT_T; ++r) {
        int j = tid + r * FFT_T;
        if (j == 0) {
            #pragma unroll
            for (int q = 0; q < 2; ++q) {
                float p0 = sre[q][0], pn = s_nyq[q];
                zr[q][r] = 0.5f * (p0 + pn);
                zi[q][r] = 0.5f * (p0 - pn);
            }
        } else {
            int k = rev12(j);
            int p = rev12(NH - k);
            float2 w = g_tw[k];
            #pragma unroll
            for (int q = 0; q < 2; ++q) {
                float pjr = sre[q][j], pji = sim[q][j];
                float ppr = sre[q][p], ppi = sim[q][p];
                float Xer = 0.5f * (pjr + ppr), Xei = 0.5f * (pji - ppi);
                float Dr  = 0.5f * (pjr - ppr), Di  = 0.5f * (pji + ppi);
                float Xor = w.x * Dr + w.y * Di;
                float Xoi = w.x * Di - w.y * Dr;
                zr[q][r] = Xer - Xoi;
                zi[q][r] = Xei + Xor;
            }
        }
    }
    __syncthreads();
    #pragma unroll
    for (int r = 0; r < NH / FFT_T; ++r) {
        int j = tid + r * FFT_T;
        sre[0][j] = zr[0][r]; sim[0][j] = zi[0][r];
        sre[1][j] = zr[1][r]; sim[1][j] = zi[1][r];
    }
    __syncthreads();

    // fused dual radix-2^2 inverse DIT (stage pairs s, s+1)
    #pragma unroll
    for (int s = 0; s < LOGH; s += 2) {
        int m = 1 << s;
        #pragma unroll
        for (int r = 0; r < (NH / 4) / FFT_T; ++r) {
            int k = tid + r * FFT_T;
            int j = k & (m - 1);
            int base = ((k >> s) << (s + 2)) + j;
            int ia = base, ib = base + m, ic = base + 2 * m, id = base + 3 * m;
            float2 w1 = g_tw[j << (LOGH - s)];
            float2 w2 = g_tw[j << (LOGH - s - 1)];
            #pragma unroll
            for (int q = 0; q < 2; ++q) {
                float ar = sre[q][ia], ai = sim[q][ia];
                float br = sre[q][ib], bi = sim[q][ib];
                float cr = sre[q][ic], ci = sim[q][ic];
                float dr = sre[q][id], di = sim[q][id];
                // stage s (conj w1): pairs (a,b) and (c,d)
                float vr = br * w1.x + bi * w1.y;
                float vi = bi * w1.x - br * w1.y;
                float a1r = ar + vr, a1i = ai + vi;
                float b1r = ar - vr, b1i = ai - vi;
                vr = dr * w1.x + di * w1.y;
                vi = di * w1.x - dr * w1.y;
                float c1r = cr + vr, c1i = ci + vi;
                float d1r = cr - vr, d1i = ci - vi;
                // stage s+1: pairs (a1,c1) conj(w2) ; (b1,d1) conj(w2)*i
                float tr = c1r * w2.x + c1i * w2.y;
                float ti = c1i * w2.x - c1r * w2.y;
                sre[q][ia] = a1r + tr;  sim[q][ia] = a1i + ti;
                sre[q][ic] = a1r - tr;  sim[q][ic] = a1i - ti;
                float ur = d1r * w2.x + d1i * w2.y;
                float ui = d1i * w2.x - d1r * w2.y;
                // * i : (ur,ui) -> (-ui, ur)
                sre[q][ib] = b1r - ui;  sim[q][ib] = b1i + ur;
                sre[q][id] = b1r + ui;  sim[q][id] = b1i - ur;
            }
        }
        __syncthreads();
    }

    const float inv_n = 1.0f / 4096.0f;
    #pragma unroll
    for (int q = 0; q < 2; ++q) {
        float2* m2 = (float2*)(g_m + (size_t)((b0 + q) * HID + h) * SEQ);
        #pragma unroll
        for (int r = 0; r < (SEQ / 2) / FFT_T; ++r) {
            int n = tid + r * FFT_T;
            float2 v;
            v.x = sre[q][n] * inv_n;
            v.y = sim[q][n] * inv_n;
            m2[n] = v;
        }
    }
}

// ---------------- fuse: out[b][t][h] = relu(m + hx), transposed -------------------
__global__ void fuse_kernel(float* __restrict__ out) {
    __shared__ float tile[32][33];
    int b  = blockIdx.z;
    int h0 = blockIdx.y * 32;
    int t0 = blockIdx.x * 32;
    int tx = threadIdx.x, ty = threadIdx.y;
    #pragma unroll
    for (int r = 0; r < 32; r += 8) {
        size_t src = (size_t)(b * HID + h0 + ty + r) * SEQ + t0 + tx;
        tile[ty + r][tx] = fmaxf(g_m[src] + g_hx[src], 0.f);
    }
    __syncthreads();
    #pragma unroll
    for (int r = 0; r < 32; r += 8)
        out[(size_t)(b * SEQ + t0 + ty + r) * HID + h0 + tx] = tile[tx][ty + r];
}

// ---------------- h[:, -1, :] appended after h -------------------------------------
__global__ void last_kernel(float* __restrict__ out) {
    int i = blockIdx.x * blockDim.x + threadIdx.x;
    if (i < BATCH * HID) {
        size_t idx = (size_t)i * SEQ + (SEQ - 1);
        out[(size_t)BATCH * SEQ * HID + i] = fmaxf(g_m[idx] + g_hx[idx], 0.f);
    }
}

// ---------------- launch ------------------------------------------------------------
extern "C" void kernel_launch(void* const* d_in, const int* in_sizes, int n_in,
                              void* d_out, int out_size) {
    const float* x    = (const float*)d_in[0];
    const float* Wu_w = (const float*)d_in[1];
    const float* Wu_b = (const float*)d_in[2];
    const float* Wh_w = (const float*)d_in[3];
    const float* Wh_b = (const float*)d_in[4];
    const float* H    = (const float*)d_in[5];
    float* out = (float*)d_out;

    twiddle_kernel<<<8, 512>>>();
    u_kernel<<<(BATCH * SEQ * 32) / 256, 256>>>(x, Wu_w, Wu_b);

    fft_fwd_kernel<<<32,    FFT_T>>>(nullptr, 0);   // u spectra (half, bitrev)
    fft_fwd_kernel<<<ORDER, FFT_T>>>(H, 1);         // H spectra (half, bitrev)

    gbuild_bf16_kernel<<<dim3(KS / 64, HID / 64, MD), 256>>>(Wh_w);
    hx_bf16_kernel<<<dim3(SEQ / 128, HID / 64, BATCH), 256>>>(x, Wh_w, Wh_b);

    pifft_kernel<<<HID * BATCH / 2, FFT_T>>>();

    fuse_kernel<<<dim3(SEQ / 32, HID / 32, BATCH), dim3(32, 8)>>>(out);
    if (out_size >= BATCH * SEQ * HID + BATCH * HID)
        last_kernel<<<8, 512>>>(out);
}

// round 6
// speedup vs baseline: 1.0391x; 1.0391x over previous
#include <cuda_runtime.h>
#include <cuda_bf16.h>
#include <mma.h>
#include <math.h>

using namespace nvcuda;

#define SEQ   4096
#define BATCH 8
#define MD    4
#define ORDER 256
#define INPUT 256
#define HID   512
#define MSZ   1280
#define NH    4096      // complex FFT size (= 8192/2), real-FFT packing
#define LOGH  12
#define KS    4160      // spectrum row stride: 4096 bitrev slots + nyquist + pad
#define FFT_T 512

typedef wmma::fragment<wmma::matrix_a, 16, 16, 16, __nv_bfloat16, wmma::row_major> FA;
typedef wmma::fragment<wmma::matrix_b, 16, 16, 16, __nv_bfloat16, wmma::row_major> FBr;
typedef wmma::fragment<wmma::matrix_b, 16, 16, 16, __nv_bfloat16, wmma::col_major> FBc;
typedef wmma::fragment<wmma::accumulator, 16, 16, 16, float> FC;

// ---------------- scratch (static device globals; no allocation) ----------------
__device__ float  g_u  [32 * SEQ];
__device__ float2 g_tw [NH];            // e^{-2*pi*i*k/8192}
__device__ float  g_Ure[32 * KS];
__device__ float  g_Uim[32 * KS];
__device__ float  g_Hre[ORDER * KS];
__device__ float  g_Him[ORDER * KS];
__device__ float  g_Gre[HID * MD * KS];
__device__ float  g_Gim[HID * MD * KS];
__device__ float  g_hx [BATCH * HID * SEQ];  // h (pre-relu then relu'd), [b][h][t]

__device__ __forceinline__ int rev12(int x) { return (int)(__brev((unsigned)x) >> 20); }

__device__ __forceinline__ void bsplit(float v, __nv_bfloat16& hi, __nv_bfloat16& lo) {
    hi = __float2bfloat16(v);
    lo = __float2bfloat16(v - __bfloat162float(hi));
}

// ---------------- twiddle table --------------------------------------------------
__global__ void twiddle_kernel() {
    int k = blockIdx.x * blockDim.x + threadIdx.x;
    if (k < NH) {
        float s, c;
        sincospif(-(float)k / 4096.0f, &s, &c);
        g_tw[k] = make_float2(c, s);
    }
}

// ---------------- u = relu(x @ Wu^T + b) ------------------------------------------
__global__ void u_kernel(const float* __restrict__ x,
                         const float* __restrict__ Wu_w,
                         const float* __restrict__ Wu_b) {
    int gw   = (blockIdx.x * blockDim.x + threadIdx.x) >> 5;
    int lane = threadIdx.x & 31;
    if (gw >= BATCH * SEQ) return;
    int b = gw >> 12, t = gw & (SEQ - 1);
    const float* xp = x + (size_t)(b * SEQ + t) * INPUT;
    float a0 = 0.f, a1 = 0.f, a2 = 0.f, a3 = 0.f;
    #pragma unroll
    for (int i = lane; i < INPUT; i += 32) {
        float xv = xp[i];
        a0 = fmaf(xv, __ldg(&Wu_w[0 * INPUT + i]), a0);
        a1 = fmaf(xv, __ldg(&Wu_w[1 * INPUT + i]), a1);
        a2 = fmaf(xv, __ldg(&Wu_w[2 * INPUT + i]), a2);
        a3 = fmaf(xv, __ldg(&Wu_w[3 * INPUT + i]), a3);
    }
    #pragma unroll
    for (int off = 16; off; off >>= 1) {
        a0 += __shfl_down_sync(0xffffffffu, a0, off);
        a1 += __shfl_down_sync(0xffffffffu, a1, off);
        a2 += __shfl_down_sync(0xffffffffu, a2, off);
        a3 += __shfl_down_sync(0xffffffffu, a3, off);
    }
    if (lane == 0) {
        g_u[(b * 4 + 0) * SEQ + t] = fmaxf(a0 + Wu_b[0], 0.f);
        g_u[(b * 4 + 1) * SEQ + t] = fmaxf(a1 + Wu_b[1], 0.f);
        g_u[(b * 4 + 2) * SEQ + t] = fmaxf(a2 + Wu_b[2], 0.f);
        g_u[(b * 4 + 3) * SEQ + t] = fmaxf(a3 + Wu_b[3], 0.f);
    }
}

// ---------------- forward real FFT (radix-2^2 DIF, half spectrum, bitrev slots) ---
__global__ void fft_fwd_kernel(const float* __restrict__ Hin, int mode) {
    __shared__ float sre[NH];
    __shared__ float sim[NH];
    int row = blockIdx.x;
    int tid = threadIdx.x;
    const float* in = mode ? (Hin + (size_t)row * SEQ) : (g_u + (size_t)row * SEQ);
    float* outre = mode ? (g_Hre + (size_t)row * KS) : (g_Ure + (size_t)row * KS);
    float* outim = mode ? (g_Him + (size_t)row * KS) : (g_Uim + (size_t)row * KS);

    const float2* in2 = (const float2*)in;
    #pragma unroll
    for (int r = 0; r < NH / FFT_T; ++r) {
        int n = tid + r * FFT_T;
        if (n < SEQ / 2) { float2 v = in2[n]; sre[n] = v.x; sim[n] = v.y; }
        else             { sre[n] = 0.f;      sim[n] = 0.f; }
    }
    __syncthreads();

    // fused DIF stage pairs (s+1, s), s = LOGH-2 .. 0
    #pragma unroll
    for (int s = LOGH - 2; s >= 0; s -= 2) {
        int m = 1 << s;
        #pragma unroll
        for (int r = 0; r < (NH / 4) / FFT_T; ++r) {
            int k = tid + r * FFT_T;
            int j = k & (m - 1);
            int base = ((k >> s) << (s + 2)) + j;
            int ia = base, ib = base + m, ic = base + 2 * m, id = base + 3 * m;
            float2 w2 = g_tw[j << (LOGH - s - 1)];
            float2 w1 = g_tw[j << (LOGH - s)];
            float ar = sre[ia], ai = sim[ia];
            float br = sre[ib], bi = sim[ib];
            float cr = sre[ic], ci = sim[ic];
            float dr = sre[id], di = sim[id];
            float a1r = ar + cr, a1i = ai + ci;
            float tr  = ar - cr, ti  = ai - ci;
            float c1r = tr * w2.x - ti * w2.y;
            float c1i = tr * w2.y + ti * w2.x;
            float b1r = br + dr, b1i = bi + di;
            tr = br - dr; ti = bi - di;
            float er = tr * w2.x - ti * w2.y;
            float ei = tr * w2.y + ti * w2.x;
            float d1r = ei, d1i = -er;                     // * (-i)
            sre[ia] = a1r + b1r;  sim[ia] = a1i + b1i;
            tr = a1r - b1r; ti = a1i - b1i;
            sre[ib] = tr * w1.x - ti * w1.y;
            sim[ib] = tr * w1.y + ti * w1.x;
            sre[ic] = c1r + d1r;  sim[ic] = c1i + d1i;
            tr = c1r - d1r; ti = c1i - d1i;
            sre[id] = tr * w1.x - ti * w1.y;
            sim[id] = tr * w1.y + ti * w1.x;
        }
        __syncthreads();
    }

    #pragma unroll
    for (int r = 0; r < NH / FFT_T; ++r) {
        int j = tid + r * FFT_T;
        if (j == 0) {
            float zr = sre[0], zi = sim[0];
            outre[0]  = zr + zi;  outim[0]  = 0.f;
            outre[NH] = zr - zi;  outim[NH] = 0.f;
        } else {
            int k = rev12(j);
            int p = rev12(NH - k);
            float zjr = sre[j], zji = sim[j];
            float zpr = sre[p], zpi = sim[p];
            float Ar = 0.5f * (zjr + zpr), Ai = 0.5f * (zji - zpi);
            float Br = 0.5f * (zji + zpi), Bi = -0.5f * (zjr - zpr);
            float2 w = g_tw[k];
            outre[j] = Ar + w.x * Br - w.y * Bi;
            outim[j] = Ai + w.x * Bi + w.y * Br;
        }
    }
}

// ---------------- G[h,d,:] = sum_o Wh[h, d*256+o] * Hspec[o,:]  (bf16 split) ------
__global__ __launch_bounds__(256)
void gbuild_bf16_kernel(const float* __restrict__ Wh_w) {
    __shared__ __nv_bfloat16 sAhi[64][40], sAlo[64][40];        // [m][k]
    __shared__ __nv_bfloat16 sBhi[2][32][72], sBlo[2][32][72];  // [re/im][k][n]
    int d  = blockIdx.z;
    int h0 = blockIdx.y * 64;
    int k0 = blockIdx.x * 64;
    int tid = threadIdx.x;
    int w  = tid >> 5;
    int wm = w & 3;
    int wn = w >> 2;

    FC accr[2], acci[2];
    #pragma unroll
    for (int j = 0; j < 2; ++j) { wmma::fill_fragment(accr[j], 0.f); wmma::fill_fragment(acci[j], 0.f); }

    for (int o0 = 0; o0 < ORDER; o0 += 32) {
        #pragma unroll
        for (int r = 0; r < 8; ++r) {
            int e = tid + r * 256;
            int m = e >> 5, kk = e & 31;
            float v = Wh_w[(size_t)(h0 + m) * MSZ + d * ORDER + o0 + kk];
            bsplit(v, sAhi[m][kk], sAlo[m][kk]);
        }
        #pragma unroll
        for (int r = 0; r < 8; ++r) {
            int e = tid + r * 256;
            int oo = e >> 6, nn = e & 63;
            size_t src = (size_t)(o0 + oo) * KS + k0 + nn;
            bsplit(g_Hre[src], sBhi[0][oo][nn], sBlo[0][oo][nn]);
            bsplit(g_Him[src], sBhi[1][oo][nn], sBlo[1][oo][nn]);
        }
        __syncthreads();
        #pragma unroll
        for (int kk = 0; kk < 32; kk += 16) {
            FA ahi, alo;
            wmma::load_matrix_sync(ahi, &sAhi[wm * 16][kk], 40);
            wmma::load_matrix_sync(alo, &sAlo[wm * 16][kk], 40);
            #pragma unroll
            for (int j = 0; j < 2; ++j) {
                FBr bhi, blo;
                wmma::load_matrix_sync(bhi, &sBhi[0][kk][wn * 32 + j * 16], 72);
                wmma::load_matrix_sync(blo, &sBlo[0][kk][wn * 32 + j * 16], 72);
                wmma::mma_sync(accr[j], ahi, bhi, accr[j]);
                wmma::mma_sync(accr[j], alo, bhi, accr[j]);
                wmma::mma_sync(accr[j], ahi, blo, accr[j]);
                wmma::load_matrix_sync(bhi, &sBhi[1][kk][wn * 32 + j * 16], 72);
                wmma::load_matrix_sync(blo, &sBlo[1][kk][wn * 32 + j * 16], 72);
                wmma::mma_sync(acci[j], ahi, bhi, acci[j]);
                wmma::mma_sync(acci[j], alo, bhi, acci[j]);
                wmma::mma_sync(acci[j], ahi, blo, acci[j]);
            }
        }
        __syncthreads();
    }
    #pragma unroll
    for (int j = 0; j < 2; ++j) {
        size_t dst = ((size_t)(h0 + wm * 16) * MD + d) * KS + k0 + wn * 32 + j * 16;
        wmma::store_matrix_sync(&g_Gre[dst], accr[j], MD * KS, wmma::mem_row_major);
        wmma::store_matrix_sync(&g_Gim[dst], acci[j], MD * KS, wmma::mem_row_major);
    }
}

// ---------------- hx[b,h,t] = sum_i Wh[h,1024+i]*x[b,t,i] + Wh_b[h]  (bf16) -------
__global__ __launch_bounds__(256)
void hx_bf16_kernel(const float* __restrict__ x,
                    const float* __restrict__ Wh_w,
                    const float* __restrict__ Wh_b) {
    __shared__ __nv_bfloat16 sAhi[64][40], sAlo[64][40];    // [h][i]
    __shared__ __nv_bfloat16 sBhi[128][40], sBlo[128][40];  // [t][i]
    __shared__ float sBias[64][16];
    int b  = blockIdx.z;
    int h0 = blockIdx.y * 64;
    int t0 = blockIdx.x * 128;
    int tid = threadIdx.x;
    int w  = tid >> 5;
    int wm = w & 3;
    int wn = w >> 2;

    #pragma unroll
    for (int r = 0; r < 4; ++r) {
        int e = tid + r * 256;
        sBias[e >> 4][e & 15] = Wh_b[h0 + (e >> 4)];
    }
    __syncthreads();

    FC acc[4];
    #pragma unroll
    for (int j = 0; j < 4; ++j)
        wmma::load_matrix_sync(acc[j], &sBias[wm * 16][0], 16, wmma::mem_row_major);

    const float4* x4 = (const float4*)(x + (size_t)(b * SEQ + t0) * INPUT);
    for (int i0 = 0; i0 < INPUT; i0 += 32) {
        #pragma unroll
        for (int r = 0; r < 8; ++r) {
            int e = tid + r * 256;
            int m = e >> 5, kk = e & 31;
            float v = Wh_w[(size_t)(h0 + m) * MSZ + MD * ORDER + i0 + kk];
            bsplit(v, sAhi[m][kk], sAlo[m][kk]);
        }
        #pragma unroll
        for (int r = 0; r < 4; ++r) {
            int e = tid + r * 256;
            int tt = e >> 3, q = e & 7;
            float4 v = x4[(size_t)tt * (INPUT / 4) + (i0 >> 2) + q];
            bsplit(v.x, sBhi[tt][q * 4 + 0], sBlo[tt][q * 4 + 0]);
            bsplit(v.y, sBhi[tt][q * 4 + 1], sBlo[tt][q * 4 + 1]);
            bsplit(v.z, sBhi[tt][q * 4 + 2], sBlo[tt][q * 4 + 2]);
            bsplit(v.w, sBhi[tt][q * 4 + 3], sBlo[tt][q * 4 + 3]);
        }
        __syncthreads();
        #pragma unroll
        for (int kk = 0; kk < 32; kk += 16) {
            FA ahi, alo;
            wmma::load_matrix_sync(ahi, &sAhi[wm * 16][kk], 40);
            wmma::load_matrix_sync(alo, &sAlo[wm * 16][kk], 40);
            #pragma unroll
            for (int j = 0; j < 4; ++j) {
                FBc bhi, blo;
                wmma::load_matrix_sync(bhi, &sBhi[wn * 64 + j * 16][kk], 40);
                wmma::load_matrix_sync(blo, &sBlo[wn * 64 + j * 16][kk], 40);
                wmma::mma_sync(acc[j], ahi, bhi, acc[j]);
                wmma::mma_sync(acc[j], alo, bhi, acc[j]);
                wmma::mma_sync(acc[j], ahi, blo, acc[j]);
            }
        }
        __syncthreads();
    }
    #pragma unroll
    for (int j = 0; j < 4; ++j) {
        size_t dst = ((size_t)b * HID + h0 + wm * 16) * SEQ + t0 + wn * 64 + j * 16;
        wmma::store_matrix_sync(&g_hx[dst], acc[j], SEQ, wmma::mem_row_major);
    }
}

// ---------------- P = sum_d G*U ; real-iFFT (radix-2^2, 2 batches/block) ----------
__global__ __launch_bounds__(FFT_T)
void pifft_kernel() {
    __shared__ float sre[2][NH];
    __shared__ float sim[2][NH];
    __shared__ float s_nyq[2];
    int h  = blockIdx.x >> 2;
    int bp = blockIdx.x & 3;
    int b0 = bp * 2;
    int tid = threadIdx.x;

    const float* Ur0 = g_Ure + (size_t)b0 * MD * KS;
    const float* Ui0 = g_Uim + (size_t)b0 * MD * KS;
    const float* Ur1 = Ur0 + MD * KS;
    const float* Ui1 = Ui0 + MD * KS;
    const float* Gr  = g_Gre + (size_t)h * MD * KS;
    const float* Gi  = g_Gim + (size_t)h * MD * KS;

    #pragma unroll
    for (int r = 0; r < NH / FFT_T; ++r) {
        int j = tid + r * FFT_T;
        float pr0 = 0.f, pi0 = 0.f, pr1 = 0.f, pi1 = 0.f;
        #pragma unroll
        for (int d = 0; d < MD; ++d) {
            float gr = Gr[d * KS + j], gi = Gi[d * KS + j];
            float ur = Ur0[d * KS + j], ui = Ui0[d * KS + j];
            pr0 += ur * gr - ui * gi;
            pi0 += ur * gi + ui * gr;
            ur = Ur1[d * KS + j]; ui = Ui1[d * KS + j];
            pr1 += ur * gr - ui * gi;
            pi1 += ur * gi + ui * gr;
        }
        sre[0][j] = pr0; sim[0][j] = pi0;
        sre[1][j] = pr1; sim[1][j] = pi1;
    }
    if (tid < 2) {
        const float* Urb = tid ? Ur1 : Ur0;
        const float* Uib = tid ? Ui1 : Ui0;
        float pn = 0.f;
        #pragma unroll
        for (int d = 0; d < MD; ++d)
            pn += Urb[d * KS + NH] * Gr[d * KS + NH] - Uib[d * KS + NH] * Gi[d * KS + NH];
        s_nyq[tid] = pn;
    }
    __syncthreads();

    // inverse untangle pack (bit-reversed slots)
    float zr[2][NH / FFT_T], zi[2][NH / FFT_T];
    #pragma unroll
    for (int r = 0; r < NH / FFT_T; ++r) {
        int j = tid + r * FFT_T;
        if (j == 0) {
            #pragma unroll
            for (int q = 0; q < 2; ++q) {
                float p0 = sre[q][0], pn = s_nyq[q];
                zr[q][r] = 0.5f * (p0 + pn);
                zi[q][r] = 0.5f * (p0 - pn);
            }
        } else {
            int k = rev12(j);
            int p = rev12(NH - k);
            float2 w = g_tw[k];
            #pragma unroll
            for (int q = 0; q < 2; ++q) {
                float pjr = sre[q][j], pji = sim[q][j];
                float ppr = sre[q][p], ppi = sim[q][p];
                float Xer = 0.5f * (pjr + ppr), Xei = 0.5f * (pji - ppi);
                float Dr  = 0.5f * (pjr - ppr), Di  = 0.5f * (pji + ppi);
                float Xor = w.x * Dr + w.y * Di;
                float Xoi = w.x * Di - w.y * Dr;
                zr[q][r] = Xer - Xoi;
                zi[q][r] = Xei + Xor;
            }
        }
    }
    __syncthreads();
    #pragma unroll
    for (int r = 0; r < NH / FFT_T; ++r) {
        int j = tid + r * FFT_T;
        sre[0][j] = zr[0][r]; sim[0][j] = zi[0][r];
        sre[1][j] = zr[1][r]; sim[1][j] = zi[1][r];
    }
    __syncthreads();

    // fused dual radix-2^2 inverse DIT (stage pairs s, s+1)
    #pragma unroll
    for (int s = 0; s < LOGH; s += 2) {
        int m = 1 << s;
        #pragma unroll
        for (int r = 0; r < (NH / 4) / FFT_T; ++r) {
            int k = tid + r * FFT_T;
            int j = k & (m - 1);
            int base = ((k >> s) << (s + 2)) + j;
            int ia = base, ib = base + m, ic = base + 2 * m, id = base + 3 * m;
            float2 w1 = g_tw[j << (LOGH - s)];
            float2 w2 = g_tw[j << (LOGH - s - 1)];
            #pragma unroll
            for (int q = 0; q < 2; ++q) {
                float ar = sre[q][ia], ai = sim[q][ia];
                float br = sre[q][ib], bi = sim[q][ib];
                float cr = sre[q][ic], ci = sim[q][ic];
                float dr = sre[q][id], di = sim[q][id];
                float vr = br * w1.x + bi * w1.y;
                float vi = bi * w1.x - br * w1.y;
                float a1r = ar + vr, a1i = ai + vi;
                float b1r = ar - vr, b1i = ai - vi;
                vr = dr * w1.x + di * w1.y;
                vi = di * w1.x - dr * w1.y;
                float c1r = cr + vr, c1i = ci + vi;
                float d1r = cr - vr, d1i = ci - vi;
                float tr = c1r * w2.x + c1i * w2.y;
                float ti = c1i * w2.x - c1r * w2.y;
                sre[q][ia] = a1r + tr;  sim[q][ia] = a1i + ti;
                sre[q][ic] = a1r - tr;  sim[q][ic] = a1i - ti;
                float ur = d1r * w2.x + d1i * w2.y;
                float ui = d1i * w2.x - d1r * w2.y;
                sre[q][ib] = b1r - ui;  sim[q][ib] = b1i + ur;
                sre[q][id] = b1r + ui;  sim[q][id] = b1i - ur;
            }
        }
        __syncthreads();
    }

    const float inv_n = 1.0f / 4096.0f;
    #pragma unroll
    for (int q = 0; q < 2; ++q) {
        float2* hx2 = (float2*)(g_hx + (size_t)((b0 + q) * HID + h) * SEQ);
        #pragma unroll
        for (int r = 0; r < (SEQ / 2) / FFT_T; ++r) {
            int n = tid + r * FFT_T;
            float2 old = hx2[n];
            float2 v;
            v.x = fmaxf(fmaf(sre[q][n], inv_n, old.x), 0.f);
            v.y = fmaxf(fmaf(sim[q][n], inv_n, old.y), 0.f);
            hx2[n] = v;
        }
    }
}

// ---------------- transpose [b][h][t] -> out [b][t][h] ----------------------------
__global__ void fuse_kernel(float* __restrict__ out) {
    __shared__ float tile[32][33];
    int b  = blockIdx.z;
    int h0 = blockIdx.y * 32;
    int t0 = blockIdx.x * 32;
    int tx = threadIdx.x, ty = threadIdx.y;
    #pragma unroll
    for (int r = 0; r < 32; r += 8)
        tile[ty + r][tx] = g_hx[(size_t)(b * HID + h0 + ty + r) * SEQ + t0 + tx];
    __syncthreads();
    #pragma unroll
    for (int r = 0; r < 32; r += 8)
        out[(size_t)(b * SEQ + t0 + ty + r) * HID + h0 + tx] = tile[tx][ty + r];
}

// ---------------- h[:, -1, :] appended after h -------------------------------------
__global__ void last_kernel(float* __restrict__ out) {
    int i = blockIdx.x * blockDim.x + threadIdx.x;
    if (i < BATCH * HID)
        out[(size_t)BATCH * SEQ * HID + i] = g_hx[(size_t)i * SEQ + (SEQ - 1)];
}

// ---------------- launch ------------------------------------------------------------
extern "C" void kernel_launch(void* const* d_in, const int* in_sizes, int n_in,
                              void* d_out, int out_size) {
    const float* x    = (const float*)d_in[0];
    const float* Wu_w = (const float*)d_in[1];
    const float* Wu_b = (const float*)d_in[2];
    const float* Wh_w = (const float*)d_in[3];
    const float* Wh_b = (const float*)d_in[4];
    const float* H    = (const float*)d_in[5];
    float* out = (float*)d_out;

    twiddle_kernel<<<8, 512>>>();
    u_kernel<<<(BATCH * SEQ * 32) / 256, 256>>>(x, Wu_w, Wu_b);

    fft_fwd_kernel<<<32,    FFT_T>>>(nullptr, 0);   // u spectra (half, bitrev)
    fft_fwd_kernel<<<ORDER, FFT_T>>>(H, 1);         // H spectra (half, bitrev)

    gbuild_bf16_kernel<<<dim3(KS / 64, HID / 64, MD), 256>>>(Wh_w);
    hx_bf16_kernel<<<dim3(SEQ / 128, HID / 64, BATCH), 256>>>(x, Wh_w, Wh_b);

    pifft_kernel<<<HID * BATCH / 2, FFT_T>>>();

    fuse_kernel<<<dim3(SEQ / 32, HID / 32, BATCH), dim3(32, 8)>>>(out);
    if (out_size >= BATCH * SEQ * HID + BATCH * HID)
        last_kernel<<<8, 512>>>(out);
}

// round 7
// speedup vs baseline: 1.1209x; 1.0787x over previous
#include <cuda_runtime.h>
#include <cuda_bf16.h>
#include <mma.h>
#include <math.h>

using namespace nvcuda;

#define SEQ   4096
#define BATCH 8
#define MD    4
#define ORDER 256
#define INPUT 256
#define HID   512
#define MSZ   1280
#define NH    4096      // complex FFT size (= 8192/2), real-FFT packing
#define LOGH  12
#define KS    4160      // spectrum row stride: 4096 bitrev slots + nyquist + pad
#define FFT_T 512

typedef wmma::fragment<wmma::matrix_a, 16, 16, 16, __nv_bfloat16, wmma::row_major> FA;
typedef wmma::fragment<wmma::matrix_b, 16, 16, 16, __nv_bfloat16, wmma::row_major> FBr;
typedef wmma::fragment<wmma::matrix_b, 16, 16, 16, __nv_bfloat16, wmma::col_major> FBc;
typedef wmma::fragment<wmma::accumulator, 16, 16, 16, float> FC;

// ---------------- scratch (static device globals; zero-init, no allocation) ------
__device__ float  g_u  [32 * SEQ];
__device__ float2 g_tw [NH];            // e^{-2*pi*i*k/8192}
__device__ float  g_Ure[32 * KS];
__device__ float  g_Uim[32 * KS];
__device__ __nv_bfloat16 g_Hrehi[ORDER * KS];
__device__ __nv_bfloat16 g_Hrelo[ORDER * KS];
__device__ __nv_bfloat16 g_Himhi[ORDER * KS];
__device__ __nv_bfloat16 g_Himlo[ORDER * KS];
__device__ __nv_bfloat16 g_Whi[HID * MSZ];
__device__ __nv_bfloat16 g_Wlo[HID * MSZ];
__device__ __nv_bfloat16 g_xhi[BATCH * SEQ * INPUT];
__device__ __nv_bfloat16 g_xlo[BATCH * SEQ * INPUT];
__device__ float  g_Gre[HID * MD * KS];
__device__ float  g_Gim[HID * MD * KS];
__device__ float  g_hx [BATCH * HID * SEQ];  // h (pre-relu then relu'd), [b][h][t]

__device__ __forceinline__ int rev12(int x) { return (int)(__brev((unsigned)x) >> 20); }

__device__ __forceinline__ void bsplit(float v, __nv_bfloat16& hi, __nv_bfloat16& lo) {
    hi = __float2bfloat16(v);
    lo = __float2bfloat16(v - __bfloat162float(hi));
}

// ---------------- twiddle table ----------------------------------------------------
__global__ void twiddle_kernel() {
    int k = blockIdx.x * blockDim.x + threadIdx.x;
    if (k < NH) {
        float s, c;
        sincospif(-(float)k / 4096.0f, &s, &c);
        g_tw[k] = make_float2(c, s);
    }
}

// ---------------- one-time bf16 hi/lo splits ----------------------------------------
__global__ void wsplit_kernel(const float* __restrict__ Wh_w) {
    int i = blockIdx.x * blockDim.x + threadIdx.x;
    if (i < HID * MSZ) bsplit(Wh_w[i], g_Whi[i], g_Wlo[i]);
}
__global__ void xsplit_kernel(const float* __restrict__ x) {
    int i = blockIdx.x * blockDim.x + threadIdx.x;
    if (i < BATCH * SEQ * INPUT) bsplit(x[i], g_xhi[i], g_xlo[i]);
}

// ---------------- u = relu(x @ Wu^T + b) ---------------------------------------------
__global__ void u_kernel(const float* __restrict__ x,
                         const float* __restrict__ Wu_w,
                         const float* __restrict__ Wu_b) {
    int gw   = (blockIdx.x * blockDim.x + threadIdx.x) >> 5;
    int lane = threadIdx.x & 31;
    if (gw >= BATCH * SEQ) return;
    int b = gw >> 12, t = gw & (SEQ - 1);
    const float* xp = x + (size_t)(b * SEQ + t) * INPUT;
    float a0 = 0.f, a1 = 0.f, a2 = 0.f, a3 = 0.f;
    #pragma unroll
    for (int i = lane; i < INPUT; i += 32) {
        float xv = xp[i];
        a0 = fmaf(xv, __ldg(&Wu_w[0 * INPUT + i]), a0);
        a1 = fmaf(xv, __ldg(&Wu_w[1 * INPUT + i]), a1);
        a2 = fmaf(xv, __ldg(&Wu_w[2 * INPUT + i]), a2);
        a3 = fmaf(xv, __ldg(&Wu_w[3 * INPUT + i]), a3);
    }
    #pragma unroll
    for (int off = 16; off; off >>= 1) {
        a0 += __shfl_down_sync(0xffffffffu, a0, off);
        a1 += __shfl_down_sync(0xffffffffu, a1, off);
        a2 += __shfl_down_sync(0xffffffffu, a2, off);
        a3 += __shfl_down_sync(0xffffffffu, a3, off);
    }
    if (lane == 0) {
        g_u[(b * 4 + 0) * SEQ + t] = fmaxf(a0 + Wu_b[0], 0.f);
        g_u[(b * 4 + 1) * SEQ + t] = fmaxf(a1 + Wu_b[1], 0.f);
        g_u[(b * 4 + 2) * SEQ + t] = fmaxf(a2 + Wu_b[2], 0.f);
        g_u[(b * 4 + 3) * SEQ + t] = fmaxf(a3 + Wu_b[3], 0.f);
    }
}

// ---------------- forward real FFT (radix-2^2 DIF, half spectrum, bitrev slots) -----
// mode 0: u rows -> fp32 U spectra. mode 1: H rows -> bf16 hi/lo H spectra.
__global__ void fft_fwd_kernel(const float* __restrict__ Hin, int mode) {
    __shared__ float sre[NH];
    __shared__ float sim[NH];
    int row = blockIdx.x;
    int tid = threadIdx.x;
    const float* in = mode ? (Hin + (size_t)row * SEQ) : (g_u + (size_t)row * SEQ);

    const float2* in2 = (const float2*)in;
    #pragma unroll
    for (int r = 0; r < NH / FFT_T; ++r) {
        int n = tid + r * FFT_T;
        if (n < SEQ / 2) { float2 v = in2[n]; sre[n] = v.x; sim[n] = v.y; }
        else             { sre[n] = 0.f;      sim[n] = 0.f; }
    }
    __syncthreads();

    // fused DIF stage pairs (s+1, s)
    #pragma unroll
    for (int s = LOGH - 2; s >= 0; s -= 2) {
        int m = 1 << s;
        #pragma unroll
        for (int r = 0; r < (NH / 4) / FFT_T; ++r) {
            int k = tid + r * FFT_T;
            int j = k & (m - 1);
            int base = ((k >> s) << (s + 2)) + j;
            int ia = base, ib = base + m, ic = base + 2 * m, id = base + 3 * m;
            float2 w2 = g_tw[j << (LOGH - s - 1)];
            float2 w1 = g_tw[j << (LOGH - s)];
            float ar = sre[ia], ai = sim[ia];
            float br = sre[ib], bi = sim[ib];
            float cr = sre[ic], ci = sim[ic];
            float dr = sre[id], di = sim[id];
            float a1r = ar + cr, a1i = ai + ci;
            float tr  = ar - cr, ti  = ai - ci;
            float c1r = tr * w2.x - ti * w2.y;
            float c1i = tr * w2.y + ti * w2.x;
            float b1r = br + dr, b1i = bi + di;
            tr = br - dr; ti = bi - di;
            float er = tr * w2.x - ti * w2.y;
            float ei = tr * w2.y + ti * w2.x;
            float d1r = ei, d1i = -er;                     // * (-i)
            sre[ia] = a1r + b1r;  sim[ia] = a1i + b1i;
            tr = a1r - b1r; ti = a1i - b1i;
            sre[ib] = tr * w1.x - ti * w1.y;
            sim[ib] = tr * w1.y + ti * w1.x;
            sre[ic] = c1r + d1r;  sim[ic] = c1i + d1i;
            tr = c1r - d1r; ti = c1i - d1i;
            sre[id] = tr * w1.x - ti * w1.y;
            sim[id] = tr * w1.y + ti * w1.x;
        }
        __syncthreads();
    }

    if (mode == 0) {
        float* outre = g_Ure + (size_t)row * KS;
        float* outim = g_Uim + (size_t)row * KS;
        #pragma unroll
        for (int r = 0; r < NH / FFT_T; ++r) {
            int j = tid + r * FFT_T;
            if (j == 0) {
                float zr = sre[0], zi = sim[0];
                outre[0]  = zr + zi;  outim[0]  = 0.f;
                outre[NH] = zr - zi;  outim[NH] = 0.f;
            } else {
                int k = rev12(j);
                int p = rev12(NH - k);
                float zjr = sre[j], zji = sim[j];
                float zpr = sre[p], zpi = sim[p];
                float Ar = 0.5f * (zjr + zpr), Ai = 0.5f * (zji - zpi);
                float Br = 0.5f * (zji + zpi), Bi = -0.5f * (zjr - zpr);
                float2 w = g_tw[k];
                outre[j] = Ar + w.x * Br - w.y * Bi;
                outim[j] = Ai + w.x * Bi + w.y * Br;
            }
        }
    } else {
        size_t off = (size_t)row * KS;
        #pragma unroll
        for (int r = 0; r < NH / FFT_T; ++r) {
            int j = tid + r * FFT_T;
            float vre, vim;
            if (j == 0) {
                float zr = sre[0], zi = sim[0];
                vre = zr + zi; vim = 0.f;
                float nre = zr - zi;
                bsplit(nre, g_Hrehi[off + NH], g_Hrelo[off + NH]);
                bsplit(0.f, g_Himhi[off + NH], g_Himlo[off + NH]);
            } else {
                int k = rev12(j);
                int p = rev12(NH - k);
                float zjr = sre[j], zji = sim[j];
                float zpr = sre[p], zpi = sim[p];
                float Ar = 0.5f * (zjr + zpr), Ai = 0.5f * (zji - zpi);
                float Br = 0.5f * (zji + zpi), Bi = -0.5f * (zjr - zpr);
                float2 w = g_tw[k];
                vre = Ar + w.x * Br - w.y * Bi;
                vim = Ai + w.x * Bi + w.y * Br;
            }
            bsplit(vre, g_Hrehi[off + j], g_Hrelo[off + j]);
            bsplit(vim, g_Himhi[off + j], g_Himlo[off + j]);
        }
    }
}

// ---------------- G[h,d,:] = sum_o Wh[h, d*256+o] * Hspec[o,:]  (bf16 split) --------
__global__ __launch_bounds__(256)
void gbuild_bf16_kernel() {
    __shared__ __align__(16) __nv_bfloat16 sAhi[64][40], sAlo[64][40];        // [m][k]
    __shared__ __align__(16) __nv_bfloat16 sBhi[2][32][72], sBlo[2][32][72];  // [re/im][k][n]
    int d  = blockIdx.z;
    int h0 = blockIdx.y * 64;
    int k0 = blockIdx.x * 64;
    int tid = threadIdx.x;
    int w  = tid >> 5;
    int wm = w & 3;
    int wn = w >> 2;

    FC accr[2], acci[2];
    #pragma unroll
    for (int j = 0; j < 2; ++j) { wmma::fill_fragment(accr[j], 0.f); wmma::fill_fragment(acci[j], 0.f); }

    for (int o0 = 0; o0 < ORDER; o0 += 32) {
        {   // A tiles: 64x32, 4 uint4 per row
            int m = tid >> 2, c4 = tid & 3;
            size_t src = (size_t)(h0 + m) * MSZ + d * ORDER + o0 + c4 * 8;
            *(uint4*)&sAhi[m][c4 * 8] = *(const uint4*)&g_Whi[src];
            *(uint4*)&sAlo[m][c4 * 8] = *(const uint4*)&g_Wlo[src];
        }
        {   // B tiles: 32x64, 8 uint4 per row, 4 arrays
            int oo = tid >> 3, c4 = tid & 7;
            size_t src = (size_t)(o0 + oo) * KS + k0 + c4 * 8;
            *(uint4*)&sBhi[0][oo][c4 * 8] = *(const uint4*)&g_Hrehi[src];
            *(uint4*)&sBlo[0][oo][c4 * 8] = *(const uint4*)&g_Hrelo[src];
            *(uint4*)&sBhi[1][oo][c4 * 8] = *(const uint4*)&g_Himhi[src];
            *(uint4*)&sBlo[1][oo][c4 * 8] = *(const uint4*)&g_Himlo[src];
        }
        __syncthreads();
        #pragma unroll
        for (int kk = 0; kk < 32; kk += 16) {
            FA ahi, alo;
            wmma::load_matrix_sync(ahi, &sAhi[wm * 16][kk], 40);
            wmma::load_matrix_sync(alo, &sAlo[wm * 16][kk], 40);
            #pragma unroll
            for (int j = 0; j < 2; ++j) {
                FBr bhi, blo;
                wmma::load_matrix_sync(bhi, &sBhi[0][kk][wn * 32 + j * 16], 72);
                wmma::load_matrix_sync(blo, &sBlo[0][kk][wn * 32 + j * 16], 72);
                wmma::mma_sync(accr[j], ahi, bhi, accr[j]);
                wmma::mma_sync(accr[j], alo, bhi, accr[j]);
                wmma::mma_sync(accr[j], ahi, blo, accr[j]);
                wmma::load_matrix_sync(bhi, &sBhi[1][kk][wn * 32 + j * 16], 72);
                wmma::load_matrix_sync(blo, &sBlo[1][kk][wn * 32 + j * 16], 72);
                wmma::mma_sync(acci[j], ahi, bhi, acci[j]);
                wmma::mma_sync(acci[j], alo, bhi, acci[j]);
                wmma::mma_sync(acci[j], ahi, blo, acci[j]);
            }
        }
        __syncthreads();
    }
    #pragma unroll
    for (int j = 0; j < 2; ++j) {
        size_t dst = ((size_t)(h0 + wm * 16) * MD + d) * KS + k0 + wn * 32 + j * 16;
        wmma::store_matrix_sync(&g_Gre[dst], accr[j], MD * KS, wmma::mem_row_major);
        wmma::store_matrix_sync(&g_Gim[dst], acci[j], MD * KS, wmma::mem_row_major);
    }
}

// ---------------- hx[b,h,t] = sum_i Wh[h,1024+i]*x[b,t,i] + Wh_b[h]  (bf16) ---------
__global__ __launch_bounds__(256)
void hx_bf16_kernel(const float* __restrict__ Wh_b) {
    __shared__ __align__(16) __nv_bfloat16 sAhi[64][40], sAlo[64][40];    // [h][i]
    __shared__ __align__(16) __nv_bfloat16 sBhi[128][40], sBlo[128][40];  // [t][i]
    __shared__ float sBias[64][16];
    int b  = blockIdx.z;
    int h0 = blockIdx.y * 64;
    int t0 = blockIdx.x * 128;
    int tid = threadIdx.x;
    int w  = tid >> 5;
    int wm = w & 3;
    int wn = w >> 2;

    #pragma unroll
    for (int r = 0; r < 4; ++r) {
        int e = tid + r * 256;
        sBias[e >> 4][e & 15] = Wh_b[h0 + (e >> 4)];
    }
    __syncthreads();

    FC acc[4];
    #pragma unroll
    for (int j = 0; j < 4; ++j)
        wmma::load_matrix_sync(acc[j], &sBias[wm * 16][0], 16, wmma::mem_row_major);

    for (int i0 = 0; i0 < INPUT; i0 += 32) {
        {   // A tiles: 64x32
            int m = tid >> 2, c4 = tid & 3;
            size_t src = (size_t)(h0 + m) * MSZ + MD * ORDER + i0 + c4 * 8;
            *(uint4*)&sAhi[m][c4 * 8] = *(const uint4*)&g_Whi[src];
            *(uint4*)&sAlo[m][c4 * 8] = *(const uint4*)&g_Wlo[src];
        }
        {   // B tiles: 128x32, 4 uint4 per row, 2 rows per thread-pass
            #pragma unroll
            for (int r = 0; r < 2; ++r) {
                int e = tid + r * 256;
                int tt = e >> 2, c4 = e & 3;
                size_t src = (size_t)(b * SEQ + t0 + tt) * INPUT + i0 + c4 * 8;
                *(uint4*)&sBhi[tt][c4 * 8] = *(const uint4*)&g_xhi[src];
                *(uint4*)&sBlo[tt][c4 * 8] = *(const uint4*)&g_xlo[src];
            }
        }
        __syncthreads();
        #pragma unroll
        for (int kk = 0; kk < 32; kk += 16) {
            FA ahi, alo;
            wmma::load_matrix_sync(ahi, &sAhi[wm * 16][kk], 40);
            wmma::load_matrix_sync(alo, &sAlo[wm * 16][kk], 40);
            #pragma unroll
            for (int j = 0; j < 4; ++j) {
                FBc bhi, blo;
                wmma::load_matrix_sync(bhi, &sBhi[wn * 64 + j * 16][kk], 40);
                wmma::load_matrix_sync(blo, &sBlo[wn * 64 + j * 16][kk], 40);
                wmma::mma_sync(acc[j], ahi, bhi, acc[j]);
                wmma::mma_sync(acc[j], alo, bhi, acc[j]);
                wmma::mma_sync(acc[j], ahi, blo, acc[j]);
            }
        }
        __syncthreads();
    }
    #pragma unroll
    for (int j = 0; j < 4; ++j) {
        size_t dst = ((size_t)b * HID + h0 + wm * 16) * SEQ + t0 + wn * 64 + j * 16;
        wmma::store_matrix_sync(&g_hx[dst], acc[j], SEQ, wmma::mem_row_major);
    }
}

// ---------------- P = sum_d G*U ; real-iFFT (radix-2^2, 2 batches/block) ------------
__global__ __launch_bounds__(FFT_T)
void pifft_kernel() {
    __shared__ float sre[2][NH];
    __shared__ float sim[2][NH];
    __shared__ float s_nyq[2];
    int h  = blockIdx.x >> 2;
    int bp = blockIdx.x & 3;
    int b0 = bp * 2;
    int tid = threadIdx.x;

    const float* Ur0 = g_Ure + (size_t)b0 * MD * KS;
    const float* Ui0 = g_Uim + (size_t)b0 * MD * KS;
    const float* Ur1 = Ur0 + MD * KS;
    const float* Ui1 = Ui0 + MD * KS;
    const float* Gr  = g_Gre + (size_t)h * MD * KS;
    const float* Gi  = g_Gim + (size_t)h * MD * KS;

    #pragma unroll
    for (int r = 0; r < NH / FFT_T; ++r) {
        int j = tid + r * FFT_T;
        float pr0 = 0.f, pi0 = 0.f, pr1 = 0.f, pi1 = 0.f;
        #pragma unroll
        for (int d = 0; d < MD; ++d) {
            float gr = Gr[d * KS + j], gi = Gi[d * KS + j];
            float ur = Ur0[d * KS + j], ui = Ui0[d * KS + j];
            pr0 += ur * gr - ui * gi;
            pi0 += ur * gi + ui * gr;
            ur = Ur1[d * KS + j]; ui = Ui1[d * KS + j];
            pr1 += ur * gr - ui * gi;
            pi1 += ur * gi + ui * gr;
        }
        sre[0][j] = pr0; sim[0][j] = pi0;
        sre[1][j] = pr1; sim[1][j] = pi1;
    }
    if (tid < 2) {
        const float* Urb = tid ? Ur1 : Ur0;
        const float* Uib = tid ? Ui1 : Ui0;
        float pn = 0.f;
        #pragma unroll
        for (int d = 0; d < MD; ++d)
            pn += Urb[d * KS + NH] * Gr[d * KS + NH] - Uib[d * KS + NH] * Gi[d * KS + NH];
        s_nyq[tid] = pn;
    }
    __syncthreads();

    float zr[2][NH / FFT_T], zi[2][NH / FFT_T];
    #pragma unroll
    for (int r = 0; r < NH / FFT_T; ++r) {
        int j = tid + r * FFT_T;
        if (j == 0) {
            #pragma unroll
            for (int q = 0; q < 2; ++q) {
                float p0 = sre[q][0], pn = s_nyq[q];
                zr[q][r] = 0.5f * (p0 + pn);
                zi[q][r] = 0.5f * (p0 - pn);
            }
        } else {
            int k = rev12(j);
            int p = rev12(NH - k);
            float2 w = g_tw[k];
            #pragma unroll
            for (int q = 0; q < 2; ++q) {
                float pjr = sre[q][j], pji = sim[q][j];
                float ppr = sre[q][p], ppi = sim[q][p];
                float Xer = 0.5f * (pjr + ppr), Xei = 0.5f * (pji - ppi);
                float Dr  = 0.5f * (pjr - ppr), Di  = 0.5f * (pji + ppi);
                float Xor = w.x * Dr + w.y * Di;
                float Xoi = w.x * Di - w.y * Dr;
                zr[q][r] = Xer - Xoi;
                zi[q][r] = Xei + Xor;
            }
        }
    }
    __syncthreads();
    #pragma unroll
    for (int r = 0; r < NH / FFT_T; ++r) {
        int j = tid + r * FFT_T;
        sre[0][j] = zr[0][r]; sim[0][j] = zi[0][r];
        sre[1][j] = zr[1][r]; sim[1][j] = zi[1][r];
    }
    __syncthreads();

    #pragma unroll
    for (int s = 0; s < LOGH; s += 2) {
        int m = 1 << s;
        #pragma unroll
        for (int r = 0; r < (NH / 4) / FFT_T; ++r) {
            int k = tid + r * FFT_T;
            int j = k & (m - 1);
            int base = ((k >> s) << (s + 2)) + j;
            int ia = base, ib = base + m, ic = base + 2 * m, id = base + 3 * m;
            float2 w1 = g_tw[j << (LOGH - s)];
            float2 w2 = g_tw[j << (LOGH - s - 1)];
            #pragma unroll
            for (int q = 0; q < 2; ++q) {
                float ar = sre[q][ia], ai = sim[q][ia];
                float br = sre[q][ib], bi = sim[q][ib];
                float cr = sre[q][ic], ci = sim[q][ic];
                float dr = sre[q][id], di = sim[q][id];
                float vr = br * w1.x + bi * w1.y;
                float vi = bi * w1.x - br * w1.y;
                float a1r = ar + vr, a1i = ai + vi;
                float b1r = ar - vr, b1i = ai - vi;
                vr = dr * w1.x + di * w1.y;
                vi = di * w1.x - dr * w1.y;
                float c1r = cr + vr, c1i = ci + vi;
                float d1r = cr - vr, d1i = ci - vi;
                float tr = c1r * w2.x + c1i * w2.y;
                float ti = c1i * w2.x - c1r * w2.y;
                sre[q][ia] = a1r + tr;  sim[q][ia] = a1i + ti;
                sre[q][ic] = a1r - tr;  sim[q][ic] = a1i - ti;
                float ur = d1r * w2.x + d1i * w2.y;
                float ui = d1i * w2.x - d1r * w2.y;
                sre[q][ib] = b1r - ui;  sim[q][ib] = b1i + ur;
                sre[q][id] = b1r + ui;  sim[q][id] = b1i - ur;
            }
        }
        __syncthreads();
    }

    const float inv_n = 1.0f / 4096.0f;
    #pragma unroll
    for (int q = 0; q < 2; ++q) {
        float2* hx2 = (float2*)(g_hx + (size_t)((b0 + q) * HID + h) * SEQ);
        #pragma unroll
        for (int r = 0; r < (SEQ / 2) / FFT_T; ++r) {
            int n = tid + r * FFT_T;
            float2 old = hx2[n];
            float2 v;
            v.x = fmaxf(fmaf(sre[q][n], inv_n, old.x), 0.f);
            v.y = fmaxf(fmaf(sim[q][n], inv_n, old.y), 0.f);
            hx2[n] = v;
        }
    }
}

// ---------------- transpose [b][h][t] -> out [b][t][h] ------------------------------
__global__ void fuse_kernel(float* __restrict__ out) {
    __shared__ float tile[32][33];
    int b  = blockIdx.z;
    int h0 = blockIdx.y * 32;
    int t0 = blockIdx.x * 32;
    int tx = threadIdx.x, ty = threadIdx.y;
    #pragma unroll
    for (int r = 0; r < 32; r += 8)
        tile[ty + r][tx] = g_hx[(size_t)(b * HID + h0 + ty + r) * SEQ + t0 + tx];
    __syncthreads();
    #pragma unroll
    for (int r = 0; r < 32; r += 8)
        out[(size_t)(b * SEQ + t0 + ty + r) * HID + h0 + tx] = tile[tx][ty + r];
}

// ---------------- h[:, -1, :] appended after h ---------------------------------------
__global__ void last_kernel(float* __restrict__ out) {
    int i = blockIdx.x * blockDim.x + threadIdx.x;
    if (i < BATCH * HID)
        out[(size_t)BATCH * SEQ * HID + i] = g_hx[(size_t)i * SEQ + (SEQ - 1)];
}

// ---------------- launch --------------------------------------------------------------
extern "C" void kernel_launch(void* const* d_in, const int* in_sizes, int n_in,
                              void* d_out, int out_size) {
    const float* x    = (const float*)d_in[0];
    const float* Wu_w = (const float*)d_in[1];
    const float* Wu_b = (const float*)d_in[2];
    const float* Wh_w = (const float*)d_in[3];
    const float* Wh_b = (const float*)d_in[4];
    const float* H    = (const float*)d_in[5];
    float* out = (float*)d_out;

    twiddle_kernel<<<8, 512>>>();
    wsplit_kernel<<<(HID * MSZ + 511) / 512, 512>>>(Wh_w);
    xsplit_kernel<<<(BATCH * SEQ * INPUT + 511) / 512, 512>>>(x);
    u_kernel<<<(BATCH * SEQ * 32) / 256, 256>>>(x, Wu_w, Wu_b);

    fft_fwd_kernel<<<32,    FFT_T>>>(nullptr, 0);   // u spectra (fp32)
    fft_fwd_kernel<<<ORDER, FFT_T>>>(H, 1);         // H spectra (bf16 hi/lo)

    gbuild_bf16_kernel<<<dim3(KS / 64, HID / 64, MD), 256>>>();
    hx_bf16_kernel<<<dim3(SEQ / 128, HID / 64, BATCH), 256>>>(Wh_b);

    pifft_kernel<<<HID * BATCH / 2, FFT_T>>>();

    fuse_kernel<<<dim3(SEQ / 32, HID / 32, BATCH), dim3(32, 8)>>>(out);
    if (out_size >= BATCH * SEQ * HID + BATCH * HID)
        last_kernel<<<8, 512>>>(out);
}

// round 8
// speedup vs baseline: 1.2107x; 1.0801x over previous
#include <cuda_runtime.h>
#include <cuda_bf16.h>
#include <mma.h>
#include <math.h>

using namespace nvcuda;

#define SEQ   4096
#define BATCH 8
#define MD    4
#define ORDER 256
#define INPUT 256
#define HID   512
#define MSZ   1280
#define NH    4096      // complex FFT size (= 8192/2), real-FFT packing
#define LOGH  12
#define KS    4224      // spectrum row stride: 4096 bitrev slots + nyquist + pad (33*128)
#define FFT_T 512

typedef wmma::fragment<wmma::matrix_a, 16, 16, 16, __nv_bfloat16, wmma::row_major> FA;
typedef wmma::fragment<wmma::matrix_b, 16, 16, 16, __nv_bfloat16, wmma::row_major> FBr;
typedef wmma::fragment<wmma::matrix_b, 16, 16, 16, __nv_bfloat16, wmma::col_major> FBc;
typedef wmma::fragment<wmma::accumulator, 16, 16, 16, float> FC;

// ---------------- scratch (static device globals; no allocation) -----------------
__device__ float  g_u  [32 * SEQ];
__device__ float2 g_tw [NH];            // e^{-2*pi*i*k/8192}
__device__ float  g_Ure[32 * KS];
__device__ float  g_Uim[32 * KS];
__device__ __nv_bfloat16 g_Hrehi[ORDER * KS];
__device__ __nv_bfloat16 g_Hrelo[ORDER * KS];
__device__ __nv_bfloat16 g_Himhi[ORDER * KS];
__device__ __nv_bfloat16 g_Himlo[ORDER * KS];
__device__ __nv_bfloat16 g_Whi[HID * MSZ];
__device__ __nv_bfloat16 g_Wlo[HID * MSZ];
__device__ __nv_bfloat16 g_xhi[BATCH * SEQ * INPUT];
__device__ __nv_bfloat16 g_xlo[BATCH * SEQ * INPUT];
__device__ float  g_Gre[HID * MD * KS];
__device__ float  g_Gim[HID * MD * KS];
__device__ float  g_hx [BATCH * HID * SEQ];  // h (pre-relu then relu'd), [b][h][t]

__device__ __forceinline__ int rev12(int x) { return (int)(__brev((unsigned)x) >> 20); }

__device__ __forceinline__ void bsplit(float v, __nv_bfloat16& hi, __nv_bfloat16& lo) {
    hi = __float2bfloat16(v);
    lo = __float2bfloat16(v - __bfloat162float(hi));
}

// ---------------- twiddle table ----------------------------------------------------
__global__ void twiddle_kernel() {
    int k = blockIdx.x * blockDim.x + threadIdx.x;
    if (k < NH) {
        float s, c;
        sincospif(-(float)k / 4096.0f, &s, &c);
        g_tw[k] = make_float2(c, s);
    }
}

// ---------------- one-time bf16 hi/lo split of Wh ------------------------------------
__global__ void wsplit_kernel(const float* __restrict__ Wh_w) {
    int i = blockIdx.x * blockDim.x + threadIdx.x;
    if (i < HID * MSZ) bsplit(Wh_w[i], g_Whi[i], g_Wlo[i]);
}

// ---------------- u = relu(x @ Wu^T + b), fused x hi/lo split -------------------------
__global__ void u_kernel(const float* __restrict__ x,
                         const float* __restrict__ Wu_w,
                         const float* __restrict__ Wu_b) {
    int gw   = (blockIdx.x * blockDim.x + threadIdx.x) >> 5;
    int lane = threadIdx.x & 31;
    if (gw >= BATCH * SEQ) return;
    int b = gw >> 12, t = gw & (SEQ - 1);
    size_t rowoff = (size_t)(b * SEQ + t) * INPUT;
    const float* xp = x + rowoff;
    float a0 = 0.f, a1 = 0.f, a2 = 0.f, a3 = 0.f;
    #pragma unroll
    for (int i = lane; i < INPUT; i += 32) {
        float xv = xp[i];
        __nv_bfloat16 hi, lo;
        bsplit(xv, hi, lo);
        g_xhi[rowoff + i] = hi;
        g_xlo[rowoff + i] = lo;
        a0 = fmaf(xv, __ldg(&Wu_w[0 * INPUT + i]), a0);
        a1 = fmaf(xv, __ldg(&Wu_w[1 * INPUT + i]), a1);
        a2 = fmaf(xv, __ldg(&Wu_w[2 * INPUT + i]), a2);
        a3 = fmaf(xv, __ldg(&Wu_w[3 * INPUT + i]), a3);
    }
    #pragma unroll
    for (int off = 16; off; off >>= 1) {
        a0 += __shfl_down_sync(0xffffffffu, a0, off);
        a1 += __shfl_down_sync(0xffffffffu, a1, off);
        a2 += __shfl_down_sync(0xffffffffu, a2, off);
        a3 += __shfl_down_sync(0xffffffffu, a3, off);
    }
    if (lane == 0) {
        g_u[(b * 4 + 0) * SEQ + t] = fmaxf(a0 + Wu_b[0], 0.f);
        g_u[(b * 4 + 1) * SEQ + t] = fmaxf(a1 + Wu_b[1], 0.f);
        g_u[(b * 4 + 2) * SEQ + t] = fmaxf(a2 + Wu_b[2], 0.f);
        g_u[(b * 4 + 3) * SEQ + t] = fmaxf(a3 + Wu_b[3], 0.f);
    }
}

// ---------------- forward real FFT (radix-2^2 DIF, half spectrum, bitrev slots) ------
// mode 0: u rows -> fp32 U spectra. mode 1: H rows -> bf16 hi/lo H spectra.
__global__ void fft_fwd_kernel(const float* __restrict__ Hin, int mode) {
    __shared__ float sre[NH];
    __shared__ float sim[NH];
    int row = blockIdx.x;
    int tid = threadIdx.x;
    const float* in = mode ? (Hin + (size_t)row * SEQ) : (g_u + (size_t)row * SEQ);

    const float2* in2 = (const float2*)in;
    #pragma unroll
    for (int r = 0; r < NH / FFT_T; ++r) {
        int n = tid + r * FFT_T;
        if (n < SEQ / 2) { float2 v = in2[n]; sre[n] = v.x; sim[n] = v.y; }
        else             { sre[n] = 0.f;      sim[n] = 0.f; }
    }
    __syncthreads();

    #pragma unroll
    for (int s = LOGH - 2; s >= 0; s -= 2) {
        int m = 1 << s;
        #pragma unroll
        for (int r = 0; r < (NH / 4) / FFT_T; ++r) {
            int k = tid + r * FFT_T;
            int j = k & (m - 1);
            int base = ((k >> s) << (s + 2)) + j;
            int ia = base, ib = base + m, ic = base + 2 * m, id = base + 3 * m;
            float2 w2 = g_tw[j << (LOGH - s - 1)];
            float2 w1 = g_tw[j << (LOGH - s)];
            float ar = sre[ia], ai = sim[ia];
            float br = sre[ib], bi = sim[ib];
            float cr = sre[ic], ci = sim[ic];
            float dr = sre[id], di = sim[id];
            float a1r = ar + cr, a1i = ai + ci;
            float tr  = ar - cr, ti  = ai - ci;
            float c1r = tr * w2.x - ti * w2.y;
            float c1i = tr * w2.y + ti * w2.x;
            float b1r = br + dr, b1i = bi + di;
            tr = br - dr; ti = bi - di;
            float er = tr * w2.x - ti * w2.y;
            float ei = tr * w2.y + ti * w2.x;
            float d1r = ei, d1i = -er;                     // * (-i)
            sre[ia] = a1r + b1r;  sim[ia] = a1i + b1i;
            tr = a1r - b1r; ti = a1i - b1i;
            sre[ib] = tr * w1.x - ti * w1.y;
            sim[ib] = tr * w1.y + ti * w1.x;
            sre[ic] = c1r + d1r;  sim[ic] = c1i + d1i;
            tr = c1r - d1r; ti = c1i - d1i;
            sre[id] = tr * w1.x - ti * w1.y;
            sim[id] = tr * w1.y + ti * w1.x;
        }
        __syncthreads();
    }

    if (mode == 0) {
        float* outre = g_Ure + (size_t)row * KS;
        float* outim = g_Uim + (size_t)row * KS;
        #pragma unroll
        for (int r = 0; r < NH / FFT_T; ++r) {
            int j = tid + r * FFT_T;
            if (j == 0) {
                float zr = sre[0], zi = sim[0];
                outre[0]  = zr + zi;  outim[0]  = 0.f;
                outre[NH] = zr - zi;  outim[NH] = 0.f;
            } else {
                int k = rev12(j);
                int p = rev12(NH - k);
                float zjr = sre[j], zji = sim[j];
                float zpr = sre[p], zpi = sim[p];
                float Ar = 0.5f * (zjr + zpr), Ai = 0.5f * (zji - zpi);
                float Br = 0.5f * (zji + zpi), Bi = -0.5f * (zjr - zpr);
                float2 w = g_tw[k];
                outre[j] = Ar + w.x * Br - w.y * Bi;
                outim[j] = Ai + w.x * Bi + w.y * Br;
            }
        }
    } else {
        size_t off = (size_t)row * KS;
        #pragma unroll
        for (int r = 0; r < NH / FFT_T; ++r) {
            int j = tid + r * FFT_T;
            float vre, vim;
            if (j == 0) {
                float zr = sre[0], zi = sim[0];
                vre = zr + zi; vim = 0.f;
                float nre = zr - zi;
                bsplit(nre, g_Hrehi[off + NH], g_Hrelo[off + NH]);
                bsplit(0.f, g_Himhi[off + NH], g_Himlo[off + NH]);
                // zero the pad columns so uint4 tile loads read defined data
                for (int pcol = NH + 1; pcol < KS; ++pcol) {
                    g_Hrehi[off + pcol] = __float2bfloat16(0.f);
                    g_Hrelo[off + pcol] = __float2bfloat16(0.f);
                    g_Himhi[off + pcol] = __float2bfloat16(0.f);
                    g_Himlo[off + pcol] = __float2bfloat16(0.f);
                }
            } else {
                int k = rev12(j);
                int p = rev12(NH - k);
                float zjr = sre[j], zji = sim[j];
                float zpr = sre[p], zpi = sim[p];
                float Ar = 0.5f * (zjr + zpr), Ai = 0.5f * (zji - zpi);
                float Br = 0.5f * (zji + zpi), Bi = -0.5f * (zjr - zpr);
                float2 w = g_tw[k];
                vre = Ar + w.x * Br - w.y * Bi;
                vim = Ai + w.x * Bi + w.y * Br;
            }
            bsplit(vre, g_Hrehi[off + j], g_Hrelo[off + j]);
            bsplit(vim, g_Himhi[off + j], g_Himlo[off + j]);
        }
    }
}

// ---------------- G[h,d,:] = sum_o Wh[h, d*256+o] * Hspec[o,:]  (bf16 split) ---------
// Block tile 64(h) x 128(k); 8 warps = 2(m) x 4(n); warp tile 32x32.
__global__ __launch_bounds__(256)
void gbuild_bf16_kernel() {
    __shared__ __align__(16) __nv_bfloat16 sAhi[64][40], sAlo[64][40];         // [m][k]
    __shared__ __align__(16) __nv_bfloat16 sBhi[2][32][136], sBlo[2][32][136]; // [re/im][k][n]
    int d  = blockIdx.z;
    int h0 = blockIdx.y * 64;
    int k0 = blockIdx.x * 128;
    int tid = threadIdx.x;
    int w  = tid >> 5;
    int wm = w & 1;      // 2 m-tiles of 32
    int wn = w >> 1;     // 4 n-tiles of 32

    FC accr[2][2], acci[2][2];
    #pragma unroll
    for (int m2 = 0; m2 < 2; ++m2)
        #pragma unroll
        for (int n2 = 0; n2 < 2; ++n2) {
            wmma::fill_fragment(accr[m2][n2], 0.f);
            wmma::fill_fragment(acci[m2][n2], 0.f);
        }

    for (int o0 = 0; o0 < ORDER; o0 += 32) {
        {   // A: 64x32 (4 uint4 per row)
            int m = tid >> 2, c = (tid & 3) * 8;
            size_t src = (size_t)(h0 + m) * MSZ + d * ORDER + o0 + c;
            *(uint4*)&sAhi[m][c] = *(const uint4*)&g_Whi[src];
            *(uint4*)&sAlo[m][c] = *(const uint4*)&g_Wlo[src];
        }
        #pragma unroll
        for (int r = 0; r < 2; ++r) {   // B: 32x128, 4 arrays
            int oo = (tid >> 4) + r * 16;
            int c  = (tid & 15) * 8;
            size_t src = (size_t)(o0 + oo) * KS + k0 + c;
            *(uint4*)&sBhi[0][oo][c] = *(const uint4*)&g_Hrehi[src];
            *(uint4*)&sBlo[0][oo][c] = *(const uint4*)&g_Hrelo[src];
            *(uint4*)&sBhi[1][oo][c] = *(const uint4*)&g_Himhi[src];
            *(uint4*)&sBlo[1][oo][c] = *(const uint4*)&g_Himlo[src];
        }
        __syncthreads();
        #pragma unroll
        for (int kk = 0; kk < 32; kk += 16) {
            FA ahi[2], alo[2];
            #pragma unroll
            for (int m2 = 0; m2 < 2; ++m2) {
                wmma::load_matrix_sync(ahi[m2], &sAhi[wm * 32 + m2 * 16][kk], 40);
                wmma::load_matrix_sync(alo[m2], &sAlo[wm * 32 + m2 * 16][kk], 40);
            }
            #pragma unroll
            for (int n2 = 0; n2 < 2; ++n2) {
                FBr bhi, blo;
                wmma::load_matrix_sync(bhi, &sBhi[0][kk][wn * 32 + n2 * 16], 136);
                wmma::load_matrix_sync(blo, &sBlo[0][kk][wn * 32 + n2 * 16], 136);
                #pragma unroll
                for (int m2 = 0; m2 < 2; ++m2) {
                    wmma::mma_sync(accr[m2][n2], ahi[m2], bhi, accr[m2][n2]);
                    wmma::mma_sync(accr[m2][n2], alo[m2], bhi, accr[m2][n2]);
                    wmma::mma_sync(accr[m2][n2], ahi[m2], blo, accr[m2][n2]);
                }
                wmma::load_matrix_sync(bhi, &sBhi[1][kk][wn * 32 + n2 * 16], 136);
                wmma::load_matrix_sync(blo, &sBlo[1][kk][wn * 32 + n2 * 16], 136);
                #pragma unroll
                for (int m2 = 0; m2 < 2; ++m2) {
                    wmma::mma_sync(acci[m2][n2], ahi[m2], bhi, acci[m2][n2]);
                    wmma::mma_sync(acci[m2][n2], alo[m2], bhi, acci[m2][n2]);
                    wmma::mma_sync(acci[m2][n2], ahi[m2], blo, acci[m2][n2]);
                }
            }
        }
        __syncthreads();
    }
    #pragma unroll
    for (int m2 = 0; m2 < 2; ++m2)
        #pragma unroll
        for (int n2 = 0; n2 < 2; ++n2) {
            size_t dst = ((size_t)(h0 + wm * 32 + m2 * 16) * MD + d) * KS
                       + k0 + wn * 32 + n2 * 16;
            wmma::store_matrix_sync(&g_Gre[dst], accr[m2][n2], MD * KS, wmma::mem_row_major);
            wmma::store_matrix_sync(&g_Gim[dst], acci[m2][n2], MD * KS, wmma::mem_row_major);
        }
}

// ---------------- hx[b,h,t] = sum_i Wh[h,1024+i]*x[b,t,i] + Wh_b[h]  (bf16) ----------
__global__ __launch_bounds__(256)
void hx_bf16_kernel(const float* __restrict__ Wh_b) {
    __shared__ __align__(16) __nv_bfloat16 sAhi[64][40], sAlo[64][40];    // [h][i]
    __shared__ __align__(16) __nv_bfloat16 sBhi[128][40], sBlo[128][40];  // [t][i]
    __shared__ float sBias[64][16];
    int b  = blockIdx.z;
    int h0 = blockIdx.y * 64;
    int t0 = blockIdx.x * 128;
    int tid = threadIdx.x;
    int w  = tid >> 5;
    int wm = w & 3;
    int wn = w >> 2;

    #pragma unroll
    for (int r = 0; r < 4; ++r) {
        int e = tid + r * 256;
        sBias[e >> 4][e & 15] = Wh_b[h0 + (e >> 4)];
    }
    __syncthreads();

    FC acc[4];
    #pragma unroll
    for (int j = 0; j < 4; ++j)
        wmma::load_matrix_sync(acc[j], &sBias[wm * 16][0], 16, wmma::mem_row_major);

    for (int i0 = 0; i0 < INPUT; i0 += 32) {
        {   // A tiles: 64x32
            int m = tid >> 2, c = (tid & 3) * 8;
            size_t src = (size_t)(h0 + m) * MSZ + MD * ORDER + i0 + c;
            *(uint4*)&sAhi[m][c] = *(const uint4*)&g_Whi[src];
            *(uint4*)&sAlo[m][c] = *(const uint4*)&g_Wlo[src];
        }
        #pragma unroll
        for (int r = 0; r < 2; ++r) {   // B tiles: 128x32
            int e = tid + r * 256;
            int tt = e >> 2, c = (e & 3) * 8;
            size_t src = (size_t)(b * SEQ + t0 + tt) * INPUT + i0 + c;
            *(uint4*)&sBhi[tt][c] = *(const uint4*)&g_xhi[src];
            *(uint4*)&sBlo[tt][c] = *(const uint4*)&g_xlo[src];
        }
        __syncthreads();
        #pragma unroll
        for (int kk = 0; kk < 32; kk += 16) {
            FA ahi, alo;
            wmma::load_matrix_sync(ahi, &sAhi[wm * 16][kk], 40);
            wmma::load_matrix_sync(alo, &sAlo[wm * 16][kk], 40);
            #pragma unroll
            for (int j = 0; j < 4; ++j) {
                FBc bhi, blo;
                wmma::load_matrix_sync(bhi, &sBhi[wn * 64 + j * 16][kk], 40);
                wmma::load_matrix_sync(blo, &sBlo[wn * 64 + j * 16][kk], 40);
                wmma::mma_sync(acc[j], ahi, bhi, acc[j]);
                wmma::mma_sync(acc[j], alo, bhi, acc[j]);
                wmma::mma_sync(acc[j], ahi, blo, acc[j]);
            }
        }
        __syncthreads();
    }
    #pragma unroll
    for (int j = 0; j < 4; ++j) {
        size_t dst = ((size_t)b * HID + h0 + wm * 16) * SEQ + t0 + wn * 64 + j * 16;
        wmma::store_matrix_sync(&g_hx[dst], acc[j], SEQ, wmma::mem_row_major);
    }
}

// ---------------- P = sum_d G*U ; real-iFFT (radix-2^2, 2 batches/block) -------------
__global__ __launch_bounds__(FFT_T)
void pifft_kernel() {
    __shared__ float sre[2][NH];
    __shared__ float sim[2][NH];
    __shared__ float s_nyq[2];
    int h  = blockIdx.x >> 2;
    int bp = blockIdx.x & 3;
    int b0 = bp * 2;
    int tid = threadIdx.x;

    const float* Ur0 = g_Ure + (size_t)b0 * MD * KS;
    const float* Ui0 = g_Uim + (size_t)b0 * MD * KS;
    const float* Ur1 = Ur0 + MD * KS;
    const float* Ui1 = Ui0 + MD * KS;
    const float* Gr  = g_Gre + (size_t)h * MD * KS;
    const float* Gi  = g_Gim + (size_t)h * MD * KS;

    #pragma unroll
    for (int r = 0; r < NH / FFT_T; ++r) {
        int j = tid + r * FFT_T;
        float pr0 = 0.f, pi0 = 0.f, pr1 = 0.f, pi1 = 0.f;
        #pragma unroll
        for (int d = 0; d < MD; ++d) {
            float gr = Gr[d * KS + j], gi = Gi[d * KS + j];
            float ur = Ur0[d * KS + j], ui = Ui0[d * KS + j];
            pr0 += ur * gr - ui * gi;
            pi0 += ur * gi + ui * gr;
            ur = Ur1[d * KS + j]; ui = Ui1[d * KS + j];
            pr1 += ur * gr - ui * gi;
            pi1 += ur * gi + ui * gr;
        }
        sre[0][j] = pr0; sim[0][j] = pi0;
        sre[1][j] = pr1; sim[1][j] = pi1;
    }
    if (tid < 2) {
        const float* Urb = tid ? Ur1 : Ur0;
        const float* Uib = tid ? Ui1 : Ui0;
        float pn = 0.f;
        #pragma unroll
        for (int d = 0; d < MD; ++d)
            pn += Urb[d * KS + NH] * Gr[d * KS + NH] - Uib[d * KS + NH] * Gi[d * KS + NH];
        s_nyq[tid] = pn;
    }
    __syncthreads();

    float zr[2][NH / FFT_T], zi[2][NH / FFT_T];
    #pragma unroll
    for (int r = 0; r < NH / FFT_T; ++r) {
        int j = tid + r * FFT_T;
        if (j == 0) {
            #pragma unroll
            for (int q = 0; q < 2; ++q) {
                float p0 = sre[q][0], pn = s_nyq[q];
                zr[q][r] = 0.5f * (p0 + pn);
                zi[q][r] = 0.5f * (p0 - pn);
            }
        } else {
            int k = rev12(j);
            int p = rev12(NH - k);
            float2 w = g_tw[k];
            #pragma unroll
            for (int q = 0; q < 2; ++q) {
                float pjr = sre[q][j], pji = sim[q][j];
                float ppr = sre[q][p], ppi = sim[q][p];
                float Xer = 0.5f * (pjr + ppr), Xei = 0.5f * (pji - ppi);
                float Dr  = 0.5f * (pjr - ppr), Di  = 0.5f * (pji + ppi);
                float Xor = w.x * Dr + w.y * Di;
                float Xoi = w.x * Di - w.y * Dr;
                zr[q][r] = Xer - Xoi;
                zi[q][r] = Xei + Xor;
            }
        }
    }
    __syncthreads();
    #pragma unroll
    for (int r = 0; r < NH / FFT_T; ++r) {
        int j = tid + r * FFT_T;
        sre[0][j] = zr[0][r]; sim[0][j] = zi[0][r];
        sre[1][j] = zr[1][r]; sim[1][j] = zi[1][r];
    }
    __syncthreads();

    #pragma unroll
    for (int s = 0; s < LOGH; s += 2) {
        int m = 1 << s;
        #pragma unroll
        for (int r = 0; r < (NH / 4) / FFT_T; ++r) {
            int k = tid + r * FFT_T;
            int j = k & (m - 1);
            int base = ((k >> s) << (s + 2)) + j;
            int ia = base, ib = base + m, ic = base + 2 * m, id = base + 3 * m;
            float2 w1 = g_tw[j << (LOGH - s)];
            float2 w2 = g_tw[j << (LOGH - s - 1)];
            #pragma unroll
            for (int q = 0; q < 2; ++q) {
                float ar = sre[q][ia], ai = sim[q][ia];
                float br = sre[q][ib], bi = sim[q][ib];
                float cr = sre[q][ic], ci = sim[q][ic];
                float dr = sre[q][id], di = sim[q][id];
                float vr = br * w1.x + bi * w1.y;
                float vi = bi * w1.x - br * w1.y;
                float a1r = ar + vr, a1i = ai + vi;
                float b1r = ar - vr, b1i = ai - vi;
                vr = dr * w1.x + di * w1.y;
                vi = di * w1.x - dr * w1.y;
                float c1r = cr + vr, c1i = ci + vi;
                float d1r = cr - vr, d1i = ci - vi;
                float tr = c1r * w2.x + c1i * w2.y;
                float ti = c1i * w2.x - c1r * w2.y;
                sre[q][ia] = a1r + tr;  sim[q][ia] = a1i + ti;
                sre[q][ic] = a1r - tr;  sim[q][ic] = a1i - ti;
                float ur = d1r * w2.x + d1i * w2.y;
                float ui = d1i * w2.x - d1r * w2.y;
                sre[q][ib] = b1r - ui;  sim[q][ib] = b1i + ur;
                sre[q][id] = b1r + ui;  sim[q][id] = b1i - ur;
            }
        }
        __syncthreads();
    }

    const float inv_n = 1.0f / 4096.0f;
    #pragma unroll
    for (int q = 0; q < 2; ++q) {
        float2* hx2 = (float2*)(g_hx + (size_t)((b0 + q) * HID + h) * SEQ);
        #pragma unroll
        for (int r = 0; r < (SEQ / 2) / FFT_T; ++r) {
            int n = tid + r * FFT_T;
            float2 old = hx2[n];
            float2 v;
            v.x = fmaxf(fmaf(sre[q][n], inv_n, old.x), 0.f);
            v.y = fmaxf(fmaf(sim[q][n], inv_n, old.y), 0.f);
            hx2[n] = v;
        }
    }
}

// ---------------- transpose [b][h][t] -> out [b][t][h] -------------------------------
__global__ void fuse_kernel(float* __restrict__ out) {
    __shared__ float tile[32][33];
    int b  = blockIdx.z;
    int h0 = blockIdx.y * 32;
    int t0 = blockIdx.x * 32;
    int tx = threadIdx.x, ty = threadIdx.y;
    #pragma unroll
    for (int r = 0; r < 32; r += 8)
        tile[ty + r][tx] = g_hx[(size_t)(b * HID + h0 + ty + r) * SEQ + t0 + tx];
    __syncthreads();
    #pragma unroll
    for (int r = 0; r < 32; r += 8)
        out[(size_t)(b * SEQ + t0 + ty + r) * HID + h0 + tx] = tile[tx][ty + r];
}

// ---------------- h[:, -1, :] appended after h ----------------------------------------
__global__ void last_kernel(float* __restrict__ out) {
    int i = blockIdx.x * blockDim.x + threadIdx.x;
    if (i < BATCH * HID)
        out[(size_t)BATCH * SEQ * HID + i] = g_hx[(size_t)i * SEQ + (SEQ - 1)];
}

// ---------------- launch ---------------------------------------------------------------
extern "C" void kernel_launch(void* const* d_in, const int* in_sizes, int n_in,
                              void* d_out, int out_size) {
    const float* x    = (const float*)d_in[0];
    const float* Wu_w = (const float*)d_in[1];
    const float* Wu_b = (const float*)d_in[2];
    const float* Wh_w = (const float*)d_in[3];
    const float* Wh_b = (const float*)d_in[4];
    const float* H    = (const float*)d_in[5];
    float* out = (float*)d_out;

    twiddle_kernel<<<8, 512>>>();
    wsplit_kernel<<<(HID * MSZ + 511) / 512, 512>>>(Wh_w);
    u_kernel<<<(BATCH * SEQ * 32) / 256, 256>>>(x, Wu_w, Wu_b);

    fft_fwd_kernel<<<32,    FFT_T>>>(nullptr, 0);   // u spectra (fp32)
    fft_fwd_kernel<<<ORDER, FFT_T>>>(H, 1);         // H spectra (bf16 hi/lo)

    gbuild_bf16_kernel<<<dim3(KS / 128, HID / 64, MD), 256>>>();
    hx_bf16_kernel<<<dim3(SEQ / 128, HID / 64, BATCH), 256>>>(Wh_b);

    pifft_kernel<<<HID * BATCH / 2, FFT_T>>>();

    fuse_kernel<<<dim3(SEQ / 32, HID / 32, BATCH), dim3(32, 8)>>>(out);
    if (out_size >= BATCH * SEQ * HID + BATCH * HID)
        last_kernel<<<8, 512>>>(out);
}

// round 9
// speedup vs baseline: 1.2645x; 1.0444x over previous
#include <cuda_runtime.h>
#include <cuda_bf16.h>
#include <mma.h>
#include <math.h>

using namespace nvcuda;

#define SEQ   4096
#define BATCH 8
#define MD    4
#define ORDER 256
#define INPUT 256
#define HID   512
#define MSZ   1280
#define NH    4096      // complex FFT size (= 8192/2), real-FFT packing
#define LOGH  12
#define KS    4224      // spectrum row stride (33*128)
#define FFT_T 512

// padded smem index map: +1 word every 16 -> conflict-free radix-16 passes
#define PH(i) ((i) + ((i) >> 4))
#define SMSZ  4352      // PH(4095) = 4350, rounded up

typedef wmma::fragment<wmma::matrix_a, 16, 16, 16, __nv_bfloat16, wmma::row_major> FA;
typedef wmma::fragment<wmma::matrix_b, 16, 16, 16, __nv_bfloat16, wmma::row_major> FBr;
typedef wmma::fragment<wmma::matrix_b, 16, 16, 16, __nv_bfloat16, wmma::col_major> FBc;
typedef wmma::fragment<wmma::accumulator, 16, 16, 16, float> FC;

// ---------------- scratch (static device globals; no allocation) -----------------
__device__ float  g_u  [32 * SEQ];
__device__ float2 g_tw [NH];            // e^{-2*pi*i*k/8192}
__device__ float  g_Ure[32 * KS];
__device__ float  g_Uim[32 * KS];
__device__ __nv_bfloat16 g_Hrehi[ORDER * KS];
__device__ __nv_bfloat16 g_Hrelo[ORDER * KS];
__device__ __nv_bfloat16 g_Himhi[ORDER * KS];
__device__ __nv_bfloat16 g_Himlo[ORDER * KS];
__device__ __nv_bfloat16 g_Whi[HID * MSZ];
__device__ __nv_bfloat16 g_Wlo[HID * MSZ];
__device__ __nv_bfloat16 g_xhi[BATCH * SEQ * INPUT];
__device__ __nv_bfloat16 g_xlo[BATCH * SEQ * INPUT];
__device__ float  g_Gre[HID * MD * KS];
__device__ float  g_Gim[HID * MD * KS];
__device__ float  g_hx [BATCH * HID * SEQ];  // h (pre-relu then relu'd), [b][h][t]

__device__ __forceinline__ int rev12(int x) { return (int)(__brev((unsigned)x) >> 20); }

__device__ __forceinline__ void bsplit(float v, __nv_bfloat16& hi, __nv_bfloat16& lo) {
    hi = __float2bfloat16(v);
    lo = __float2bfloat16(v - __bfloat162float(hi));
}

// 4 radix-2 DIT stages (conj twiddles) on 16 register-resident points.
// Element t corresponds to global slot base + stride*t; jbase = base & (stride-1);
// SHIFT = 12 - log2(stride).
template<int SHIFT>
__device__ __forceinline__ void fft16_dit(float* vr_, float* vi_, int jbase, int stride) {
    #pragma unroll
    for (int ss = 0; ss < 4; ++ss) {
        int mloc = 1 << ss;
        #pragma unroll
        for (int u = 0; u < 8; ++u) {
            int t0 = ((u >> ss) << (ss + 1)) | (u & (mloc - 1));
            int t1 = t0 + mloc;
            int jg = jbase + stride * (u & (mloc - 1));
            float2 w = g_tw[jg << (SHIFT - ss)];
            float br = vr_[t1], bi = vi_[t1];
            float pr = br * w.x + bi * w.y;
            float pi = bi * w.x - br * w.y;
            float ar = vr_[t0], ai = vi_[t0];
            vr_[t0] = ar + pr;  vi_[t0] = ai + pi;
            vr_[t1] = ar - pr;  vi_[t1] = ai - pi;
        }
    }
}

// ---------------- twiddle table ----------------------------------------------------
__global__ void twiddle_kernel() {
    int k = blockIdx.x * blockDim.x + threadIdx.x;
    if (k < NH) {
        float s, c;
        sincospif(-(float)k / 4096.0f, &s, &c);
        g_tw[k] = make_float2(c, s);
    }
}

// ---------------- one-time bf16 hi/lo split of Wh ------------------------------------
__global__ void wsplit_kernel(const float* __restrict__ Wh_w) {
    int i = blockIdx.x * blockDim.x + threadIdx.x;
    if (i < HID * MSZ) bsplit(Wh_w[i], g_Whi[i], g_Wlo[i]);
}

// ---------------- u = relu(x @ Wu^T + b), fused x hi/lo split -------------------------
__global__ void u_kernel(const float* __restrict__ x,
                         const float* __restrict__ Wu_w,
                         const float* __restrict__ Wu_b) {
    int gw   = (blockIdx.x * blockDim.x + threadIdx.x) >> 5;
    int lane = threadIdx.x & 31;
    if (gw >= BATCH * SEQ) return;
    int b = gw >> 12, t = gw & (SEQ - 1);
    size_t rowoff = (size_t)(b * SEQ + t) * INPUT;
    const float* xp = x + rowoff;
    float a0 = 0.f, a1 = 0.f, a2 = 0.f, a3 = 0.f;
    #pragma unroll
    for (int i = lane; i < INPUT; i += 32) {
        float xv = xp[i];
        __nv_bfloat16 hi, lo;
        bsplit(xv, hi, lo);
        g_xhi[rowoff + i] = hi;
        g_xlo[rowoff + i] = lo;
        a0 = fmaf(xv, __ldg(&Wu_w[0 * INPUT + i]), a0);
        a1 = fmaf(xv, __ldg(&Wu_w[1 * INPUT + i]), a1);
        a2 = fmaf(xv, __ldg(&Wu_w[2 * INPUT + i]), a2);
        a3 = fmaf(xv, __ldg(&Wu_w[3 * INPUT + i]), a3);
    }
    #pragma unroll
    for (int off = 16; off; off >>= 1) {
        a0 += __shfl_down_sync(0xffffffffu, a0, off);
        a1 += __shfl_down_sync(0xffffffffu, a1, off);
        a2 += __shfl_down_sync(0xffffffffu, a2, off);
        a3 += __shfl_down_sync(0xffffffffu, a3, off);
    }
    if (lane == 0) {
        g_u[(b * 4 + 0) * SEQ + t] = fmaxf(a0 + Wu_b[0], 0.f);
        g_u[(b * 4 + 1) * SEQ + t] = fmaxf(a1 + Wu_b[1], 0.f);
        g_u[(b * 4 + 2) * SEQ + t] = fmaxf(a2 + Wu_b[2], 0.f);
        g_u[(b * 4 + 3) * SEQ + t] = fmaxf(a3 + Wu_b[3], 0.f);
    }
}

// ---------------- forward real FFT (radix-2^2 DIF, half spectrum, bitrev slots) ------
__global__ void fft_fwd_kernel(const float* __restrict__ Hin, int mode) {
    __shared__ float sre[NH];
    __shared__ float sim[NH];
    int row = blockIdx.x;
    int tid = threadIdx.x;
    const float* in = mode ? (Hin + (size_t)row * SEQ) : (g_u + (size_t)row * SEQ);

    const float2* in2 = (const float2*)in;
    #pragma unroll
    for (int r = 0; r < NH / FFT_T; ++r) {
        int n = tid + r * FFT_T;
        if (n < SEQ / 2) { float2 v = in2[n]; sre[n] = v.x; sim[n] = v.y; }
        else             { sre[n] = 0.f;      sim[n] = 0.f; }
    }
    __syncthreads();

    #pragma unroll
    for (int s = LOGH - 2; s >= 0; s -= 2) {
        int m = 1 << s;
        #pragma unroll
        for (int r = 0; r < (NH / 4) / FFT_T; ++r) {
            int k = tid + r * FFT_T;
            int j = k & (m - 1);
            int base = ((k >> s) << (s + 2)) + j;
            int ia = base, ib = base + m, ic = base + 2 * m, id = base + 3 * m;
            float2 w2 = g_tw[j << (LOGH - s - 1)];
            float2 w1 = g_tw[j << (LOGH - s)];
            float ar = sre[ia], ai = sim[ia];
            float br = sre[ib], bi = sim[ib];
            float cr = sre[ic], ci = sim[ic];
            float dr = sre[id], di = sim[id];
            float a1r = ar + cr, a1i = ai + ci;
            float tr  = ar - cr, ti  = ai - ci;
            float c1r = tr * w2.x - ti * w2.y;
            float c1i = tr * w2.y + ti * w2.x;
            float b1r = br + dr, b1i = bi + di;
            tr = br - dr; ti = bi - di;
            float er = tr * w2.x - ti * w2.y;
            float ei = tr * w2.y + ti * w2.x;
            float d1r = ei, d1i = -er;                     // * (-i)
            sre[ia] = a1r + b1r;  sim[ia] = a1i + b1i;
            tr = a1r - b1r; ti = a1i - b1i;
            sre[ib] = tr * w1.x - ti * w1.y;
            sim[ib] = tr * w1.y + ti * w1.x;
            sre[ic] = c1r + d1r;  sim[ic] = c1i + d1i;
            tr = c1r - d1r; ti = c1i - d1i;
            sre[id] = tr * w1.x - ti * w1.y;
            sim[id] = tr * w1.y + ti * w1.x;
        }
        __syncthreads();
    }

    if (mode == 0) {
        float* outre = g_Ure + (size_t)row * KS;
        float* outim = g_Uim + (size_t)row * KS;
        #pragma unroll
        for (int r = 0; r < NH / FFT_T; ++r) {
            int j = tid + r * FFT_T;
            if (j == 0) {
                float zr = sre[0], zi = sim[0];
                outre[0]  = zr + zi;  outim[0]  = 0.f;
                outre[NH] = zr - zi;  outim[NH] = 0.f;
            } else {
                int k = rev12(j);
                int p = rev12(NH - k);
                float zjr = sre[j], zji = sim[j];
                float zpr = sre[p], zpi = sim[p];
                float Ar = 0.5f * (zjr + zpr), Ai = 0.5f * (zji - zpi);
                float Br = 0.5f * (zji + zpi), Bi = -0.5f * (zjr - zpr);
                float2 w = g_tw[k];
                outre[j] = Ar + w.x * Br - w.y * Bi;
                outim[j] = Ai + w.x * Bi + w.y * Br;
            }
        }
    } else {
        size_t off = (size_t)row * KS;
        #pragma unroll
        for (int r = 0; r < NH / FFT_T; ++r) {
            int j = tid + r * FFT_T;
            float vre, vim;
            if (j == 0) {
                float zr = sre[0], zi = sim[0];
                vre = zr + zi; vim = 0.f;
                float nre = zr - zi;
                bsplit(nre, g_Hrehi[off + NH], g_Hrelo[off + NH]);
                bsplit(0.f, g_Himhi[off + NH], g_Himlo[off + NH]);
                for (int pcol = NH + 1; pcol < KS; ++pcol) {
                    g_Hrehi[off + pcol] = __float2bfloat16(0.f);
                    g_Hrelo[off + pcol] = __float2bfloat16(0.f);
                    g_Himhi[off + pcol] = __float2bfloat16(0.f);
                    g_Himlo[off + pcol] = __float2bfloat16(0.f);
                }
            } else {
                int k = rev12(j);
                int p = rev12(NH - k);
                float zjr = sre[j], zji = sim[j];
                float zpr = sre[p], zpi = sim[p];
                float Ar = 0.5f * (zjr + zpr), Ai = 0.5f * (zji - zpi);
                float Br = 0.5f * (zji + zpi), Bi = -0.5f * (zjr - zpr);
                float2 w = g_tw[k];
                vre = Ar + w.x * Br - w.y * Bi;
                vim = Ai + w.x * Bi + w.y * Br;
            }
            bsplit(vre, g_Hrehi[off + j], g_Hrelo[off + j]);
            bsplit(vim, g_Himhi[off + j], g_Himlo[off + j]);
        }
    }
}

// ---------------- G[h,d,:] = sum_o Wh[h, d*256+o] * Hspec[o,:]  (bf16 split) ---------
__global__ __launch_bounds__(256)
void gbuild_bf16_kernel() {
    __shared__ __align__(16) __nv_bfloat16 sAhi[64][40], sAlo[64][40];         // [m][k]
    __shared__ __align__(16) __nv_bfloat16 sBhi[2][32][136], sBlo[2][32][136]; // [re/im][k][n]
    int d  = blockIdx.z;
    int h0 = blockIdx.y * 64;
    int k0 = blockIdx.x * 128;
    int tid = threadIdx.x;
    int w  = tid >> 5;
    int wm = w & 1;
    int wn = w >> 1;

    FC accr[2][2], acci[2][2];
    #pragma unroll
    for (int m2 = 0; m2 < 2; ++m2)
        #pragma unroll
        for (int n2 = 0; n2 < 2; ++n2) {
            wmma::fill_fragment(accr[m2][n2], 0.f);
            wmma::fill_fragment(acci[m2][n2], 0.f);
        }

    for (int o0 = 0; o0 < ORDER; o0 += 32) {
        {
            int m = tid >> 2, c = (tid & 3) * 8;
            size_t src = (size_t)(h0 + m) * MSZ + d * ORDER + o0 + c;
            *(uint4*)&sAhi[m][c] = *(const uint4*)&g_Whi[src];
            *(uint4*)&sAlo[m][c] = *(const uint4*)&g_Wlo[src];
        }
        #pragma unroll
        for (int r = 0; r < 2; ++r) {
            int oo = (tid >> 4) + r * 16;
            int c  = (tid & 15) * 8;
            size_t src = (size_t)(o0 + oo) * KS + k0 + c;
            *(uint4*)&sBhi[0][oo][c] = *(const uint4*)&g_Hrehi[src];
            *(uint4*)&sBlo[0][oo][c] = *(const uint4*)&g_Hrelo[src];
            *(uint4*)&sBhi[1][oo][c] = *(const uint4*)&g_Himhi[src];
            *(uint4*)&sBlo[1][oo][c] = *(const uint4*)&g_Himlo[src];
        }
        __syncthreads();
        #pragma unroll
        for (int kk = 0; kk < 32; kk += 16) {
            FA ahi[2], alo[2];
            #pragma unroll
            for (int m2 = 0; m2 < 2; ++m2) {
                wmma::load_matrix_sync(ahi[m2], &sAhi[wm * 32 + m2 * 16][kk], 40);
                wmma::load_matrix_sync(alo[m2], &sAlo[wm * 32 + m2 * 16][kk], 40);
            }
            #pragma unroll
            for (int n2 = 0; n2 < 2; ++n2) {
                FBr bhi, blo;
                wmma::load_matrix_sync(bhi, &sBhi[0][kk][wn * 32 + n2 * 16], 136);
                wmma::load_matrix_sync(blo, &sBlo[0][kk][wn * 32 + n2 * 16], 136);
                #pragma unroll
                for (int m2 = 0; m2 < 2; ++m2) {
                    wmma::mma_sync(accr[m2][n2], ahi[m2], bhi, accr[m2][n2]);
                    wmma::mma_sync(accr[m2][n2], alo[m2], bhi, accr[m2][n2]);
                    wmma::mma_sync(accr[m2][n2], ahi[m2], blo, accr[m2][n2]);
                }
                wmma::load_matrix_sync(bhi, &sBhi[1][kk][wn * 32 + n2 * 16], 136);
                wmma::load_matrix_sync(blo, &sBlo[1][kk][wn * 32 + n2 * 16], 136);
                #pragma unroll
                for (int m2 = 0; m2 < 2; ++m2) {
                    wmma::mma_sync(acci[m2][n2], ahi[m2], bhi, acci[m2][n2]);
                    wmma::mma_sync(acci[m2][n2], alo[m2], bhi, acci[m2][n2]);
                    wmma::mma_sync(acci[m2][n2], ahi[m2], blo, acci[m2][n2]);
                }
            }
        }
        __syncthreads();
    }
    #pragma unroll
    for (int m2 = 0; m2 < 2; ++m2)
        #pragma unroll
        for (int n2 = 0; n2 < 2; ++n2) {
            size_t dst = ((size_t)(h0 + wm * 32 + m2 * 16) * MD + d) * KS
                       + k0 + wn * 32 + n2 * 16;
            wmma::store_matrix_sync(&g_Gre[dst], accr[m2][n2], MD * KS, wmma::mem_row_major);
            wmma::store_matrix_sync(&g_Gim[dst], acci[m2][n2], MD * KS, wmma::mem_row_major);
        }
}

// ---------------- hx[b,h,t] = sum_i Wh[h,1024+i]*x[b,t,i] + Wh_b[h]  (bf16) ----------
__global__ __launch_bounds__(256)
void hx_bf16_kernel(const float* __restrict__ Wh_b) {
    __shared__ __align__(16) __nv_bfloat16 sAhi[64][40], sAlo[64][40];    // [h][i]
    __shared__ __align__(16) __nv_bfloat16 sBhi[128][40], sBlo[128][40];  // [t][i]
    __shared__ float sBias[64][16];
    int b  = blockIdx.z;
    int h0 = blockIdx.y * 64;
    int t0 = blockIdx.x * 128;
    int tid = threadIdx.x;
    int w  = tid >> 5;
    int wm = w & 3;
    int wn = w >> 2;

    #pragma unroll
    for (int r = 0; r < 4; ++r) {
        int e = tid + r * 256;
        sBias[e >> 4][e & 15] = Wh_b[h0 + (e >> 4)];
    }
    __syncthreads();

    FC acc[4];
    #pragma unroll
    for (int j = 0; j < 4; ++j)
        wmma::load_matrix_sync(acc[j], &sBias[wm * 16][0], 16, wmma::mem_row_major);

    for (int i0 = 0; i0 < INPUT; i0 += 32) {
        {
            int m = tid >> 2, c = (tid & 3) * 8;
            size_t src = (size_t)(h0 + m) * MSZ + MD * ORDER + i0 + c;
            *(uint4*)&sAhi[m][c] = *(const uint4*)&g_Whi[src];
            *(uint4*)&sAlo[m][c] = *(const uint4*)&g_Wlo[src];
        }
        #pragma unroll
        for (int r = 0; r < 2; ++r) {
            int e = tid + r * 256;
            int tt = e >> 2, c = (e & 3) * 8;
            size_t src = (size_t)(b * SEQ + t0 + tt) * INPUT + i0 + c;
            *(uint4*)&sBhi[tt][c] = *(const uint4*)&g_xhi[src];
            *(uint4*)&sBlo[tt][c] = *(const uint4*)&g_xlo[src];
        }
        __syncthreads();
        #pragma unroll
        for (int kk = 0; kk < 32; kk += 16) {
            FA ahi, alo;
            wmma::load_matrix_sync(ahi, &sAhi[wm * 16][kk], 40);
            wmma::load_matrix_sync(alo, &sAlo[wm * 16][kk], 40);
            #pragma unroll
            for (int j = 0; j < 4; ++j) {
                FBc bhi, blo;
                wmma::load_matrix_sync(bhi, &sBhi[wn * 64 + j * 16][kk], 40);
                wmma::load_matrix_sync(blo, &sBlo[wn * 64 + j * 16][kk], 40);
                wmma::mma_sync(acc[j], ahi, bhi, acc[j]);
                wmma::mma_sync(acc[j], alo, bhi, acc[j]);
                wmma::mma_sync(acc[j], ahi, blo, acc[j]);
            }
        }
        __syncthreads();
    }
    #pragma unroll
    for (int j = 0; j < 4; ++j) {
        size_t dst = ((size_t)b * HID + h0 + wm * 16) * SEQ + t0 + wn * 64 + j * 16;
        wmma::store_matrix_sync(&g_hx[dst], acc[j], SEQ, wmma::mem_row_major);
    }
}

// ---------------- P = sum_d G*U ; real-iFFT (3x radix-16 reg passes, 2 batches) ------
__global__ __launch_bounds__(FFT_T, 2)
void pifft_kernel() {
    __shared__ float sre[2][SMSZ];
    __shared__ float sim[2][SMSZ];
    __shared__ float s_nyq[2];
    int h  = blockIdx.x >> 2;
    int bp = blockIdx.x & 3;
    int b0 = bp * 2;
    int tid = threadIdx.x;

    const float* Ur0 = g_Ure + (size_t)b0 * MD * KS;
    const float* Ui0 = g_Uim + (size_t)b0 * MD * KS;
    const float* Ur1 = Ur0 + MD * KS;
    const float* Ui1 = Ui0 + MD * KS;
    const float* Gr  = g_Gre + (size_t)h * MD * KS;
    const float* Gi  = g_Gim + (size_t)h * MD * KS;

    // pointwise product (bit-reversed slot order), both batches
    #pragma unroll
    for (int r = 0; r < NH / FFT_T; ++r) {
        int j = tid + r * FFT_T;
        float pr0 = 0.f, pi0 = 0.f, pr1 = 0.f, pi1 = 0.f;
        #pragma unroll
        for (int d = 0; d < MD; ++d) {
            float gr = Gr[d * KS + j], gi = Gi[d * KS + j];
            float ur = Ur0[d * KS + j], ui = Ui0[d * KS + j];
            pr0 += ur * gr - ui * gi;
            pi0 += ur * gi + ui * gr;
            ur = Ur1[d * KS + j]; ui = Ui1[d * KS + j];
            pr1 += ur * gr - ui * gi;
            pi1 += ur * gi + ui * gr;
        }
        int pj = PH(j);
        sre[0][pj] = pr0; sim[0][pj] = pi0;
        sre[1][pj] = pr1; sim[1][pj] = pi1;
    }
    if (tid < 2) {
        const float* Urb = tid ? Ur1 : Ur0;
        const float* Uib = tid ? Ui1 : Ui0;
        float pn = 0.f;
        #pragma unroll
        for (int d = 0; d < MD; ++d)
            pn += Urb[d * KS + NH] * Gr[d * KS + NH] - Uib[d * KS + NH] * Gi[d * KS + NH];
        s_nyq[tid] = pn;
    }
    __syncthreads();

    // inverse untangle pack (bit-reversed slots): Z[k] = Xe[k] + i*Xo[k]
    float zr[2][NH / FFT_T], zi[2][NH / FFT_T];
    #pragma unroll
    for (int r = 0; r < NH / FFT_T; ++r) {
        int j = tid + r * FFT_T;
        if (j == 0) {
            #pragma unroll
            for (int q = 0; q < 2; ++q) {
                float p0 = sre[q][PH(0)], pn = s_nyq[q];
                zr[q][r] = 0.5f * (p0 + pn);
                zi[q][r] = 0.5f * (p0 - pn);
            }
        } else {
            int k = rev12(j);
            int p = rev12(NH - k);
            int pj = PH(j), pp = PH(p);
            float2 w = g_tw[k];
            #pragma unroll
            for (int q = 0; q < 2; ++q) {
                float pjr = sre[q][pj], pji = sim[q][pj];
                float ppr = sre[q][pp], ppi = sim[q][pp];
                float Xer = 0.5f * (pjr + ppr), Xei = 0.5f * (pji - ppi);
                float Dr  = 0.5f * (pjr - ppr), Di  = 0.5f * (pji + ppi);
                float Xor = w.x * Dr + w.y * Di;
                float Xoi = w.x * Di - w.y * Dr;
                zr[q][r] = Xer - Xoi;
                zi[q][r] = Xei + Xor;
            }
        }
    }
    __syncthreads();
    #pragma unroll
    for (int r = 0; r < NH / FFT_T; ++r) {
        int pj = PH(tid + r * FFT_T);
        sre[0][pj] = zr[0][r]; sim[0][pj] = zi[0][r];
        sre[1][pj] = zr[1][r]; sim[1][pj] = zi[1][r];
    }
    __syncthreads();

    // 3 radix-16 register passes: stages 0-3, 4-7, 8-11 (4096 = 16^3)
    {
        int q = tid >> 8;          // threads 0-255 -> fft 0; 256-511 -> fft 1
        int g = tid & 255;
        float* qre = sre[q];
        float* qim = sim[q];
        float vr_[16], vi_[16];

        // pass 1: stride 1, 16 consecutive slots (PH-contiguous)
        {
            int pb = PH(g << 4);
            #pragma unroll
            for (int t = 0; t < 16; ++t) { vr_[t] = qre[pb + t]; vi_[t] = qim[pb + t]; }
            fft16_dit<12>(vr_, vi_, 0, 1);
            #pragma unroll
            for (int t = 0; t < 16; ++t) { qre[pb + t] = vr_[t]; qim[pb + t] = vi_[t]; }
        }
        __syncthreads();
        // pass 2: stride 16
        {
            int base = ((g >> 4) << 8) + (g & 15);
            #pragma unroll
            for (int t = 0; t < 16; ++t) {
                int p = PH(base + (t << 4));
                vr_[t] = qre[p]; vi_[t] = qim[p];
            }
            fft16_dit<8>(vr_, vi_, g & 15, 16);
            #pragma unroll
            for (int t = 0; t < 16; ++t) {
                int p = PH(base + (t << 4));
                qre[p] = vr_[t]; qim[p] = vi_[t];
            }
        }
        __syncthreads();
        // pass 3: stride 256
        {
            #pragma unroll
            for (int t = 0; t < 16; ++t) {
                int p = PH(g + (t << 8));
                vr_[t] = qre[p]; vi_[t] = qim[p];
            }
            fft16_dit<4>(vr_, vi_, g, 256);
            #pragma unroll
            for (int t = 0; t < 16; ++t) {
                int p = PH(g + (t << 8));
                qre[p] = vr_[t]; qim[p] = vi_[t];
            }
        }
    }
    __syncthreads();

    // z[n] = m[2n] + i m[2n+1]; fuse add + relu into g_hx
    const float inv_n = 1.0f / 4096.0f;
    #pragma unroll
    for (int q = 0; q < 2; ++q) {
        float2* hx2 = (float2*)(g_hx + (size_t)((b0 + q) * HID + h) * SEQ);
        #pragma unroll
        for (int r = 0; r < (SEQ / 2) / FFT_T; ++r) {
            int n = tid + r * FFT_T;
            int pn = PH(n);
            float2 old = hx2[n];
            float2 v;
            v.x = fmaxf(fmaf(sre[q][pn], inv_n, old.x), 0.f);
            v.y = fmaxf(fmaf(sim[q][pn], inv_n, old.y), 0.f);
            hx2[n] = v;
        }
    }
}

// ---------------- transpose [b][h][t] -> out [b][t][h] -------------------------------
__global__ void fuse_kernel(float* __restrict__ out) {
    __shared__ float tile[32][33];
    int b  = blockIdx.z;
    int h0 = blockIdx.y * 32;
    int t0 = blockIdx.x * 32;
    int tx = threadIdx.x, ty = threadIdx.y;
    #pragma unroll
    for (int r = 0; r < 32; r += 8)
        tile[ty + r][tx] = g_hx[(size_t)(b * HID + h0 + ty + r) * SEQ + t0 + tx];
    __syncthreads();
    #pragma unroll
    for (int r = 0; r < 32; r += 8)
        out[(size_t)(b * SEQ + t0 + ty + r) * HID + h0 + tx] = tile[tx][ty + r];
}

// ---------------- h[:, -1, :] appended after h ----------------------------------------
__global__ void last_kernel(float* __restrict__ out) {
    int i = blockIdx.x * blockDim.x + threadIdx.x;
    if (i < BATCH * HID)
        out[(size_t)BATCH * SEQ * HID + i] = g_hx[(size_t)i * SEQ + (SEQ - 1)];
}

// ---------------- launch ---------------------------------------------------------------
extern "C" void kernel_launch(void* const* d_in, const int* in_sizes, int n_in,
                              void* d_out, int out_size) {
    const float* x    = (const float*)d_in[0];
    const float* Wu_w = (const float*)d_in[1];
    const float* Wu_b = (const float*)d_in[2];
    const float* Wh_w = (const float*)d_in[3];
    const float* Wh_b = (const float*)d_in[4];
    const float* H    = (const float*)d_in[5];
    float* out = (float*)d_out;

    twiddle_kernel<<<8, 512>>>();
    wsplit_kernel<<<(HID * MSZ + 511) / 512, 512>>>(Wh_w);
    u_kernel<<<(BATCH * SEQ * 32) / 256, 256>>>(x, Wu_w, Wu_b);

    fft_fwd_kernel<<<32,    FFT_T>>>(nullptr, 0);   // u spectra (fp32)
    fft_fwd_kernel<<<ORDER, FFT_T>>>(H, 1);         // H spectra (bf16 hi/lo)

    gbuild_bf16_kernel<<<dim3(KS / 128, HID / 64, MD), 256>>>();
    hx_bf16_kernel<<<dim3(SEQ / 128, HID / 64, BATCH), 256>>>(Wh_b);

    pifft_kernel<<<HID * BATCH / 2, FFT_T>>>();

    fuse_kernel<<<dim3(SEQ / 32, HID / 32, BATCH), dim3(32, 8)>>>(out);
    if (out_size >= BATCH * SEQ * HID + BATCH * HID)
        last_kernel<<<8, 512>>>(out);
}

// round 10
// speedup vs baseline: 1.3814x; 1.0924x over previous
#include <cuda_runtime.h>
#include <cuda_bf16.h>
#include <mma.h>
#include <math.h>

using namespace nvcuda;

#define SEQ   4096
#define BATCH 8
#define MD    4
#define ORDER 256
#define INPUT 256
#define HID   512
#define MSZ   1280
#define NH    4096      // complex FFT size (= 8192/2), real-FFT packing
#define LOGH  12
#define KS    4224      // spectrum row stride (33*128)
#define FFT_T 512

// padded smem index map: +1 word every 16 -> conflict-free radix-16 passes
#define PH(i) ((i) + ((i) >> 4))
#define SMSZ  4352

typedef wmma::fragment<wmma::matrix_a, 16, 16, 16, __nv_bfloat16, wmma::row_major> FA;
typedef wmma::fragment<wmma::matrix_b, 16, 16, 16, __nv_bfloat16, wmma::row_major> FBr;
typedef wmma::fragment<wmma::matrix_b, 16, 16, 16, __nv_bfloat16, wmma::col_major> FBc;
typedef wmma::fragment<wmma::accumulator, 16, 16, 16, float> FC;

// ---------------- scratch (static device globals; no allocation) -----------------
__device__ float  g_u  [32 * SEQ];
__device__ float2 g_tw [NH];            // e^{-2*pi*i*k/8192}
__device__ float  g_Ure[32 * KS];
__device__ float  g_Uim[32 * KS];
__device__ __nv_bfloat16 g_Hrehi[ORDER * KS];
__device__ __nv_bfloat16 g_Hrelo[ORDER * KS];
__device__ __nv_bfloat16 g_Himhi[ORDER * KS];
__device__ __nv_bfloat16 g_Himlo[ORDER * KS];
__device__ __nv_bfloat16 g_Whi[HID * MSZ];
__device__ __nv_bfloat16 g_Wlo[HID * MSZ];
__device__ __nv_bfloat16 g_xhi[BATCH * SEQ * INPUT];
__device__ __nv_bfloat16 g_xlo[BATCH * SEQ * INPUT];
__device__ float  g_Gre[HID * MD * KS];
__device__ float  g_Gim[HID * MD * KS];
__device__ float  g_hx [BATCH * HID * SEQ];  // h (pre-relu then relu'd), [b][h][t]

__device__ __forceinline__ int rev12(int x) { return (int)(__brev((unsigned)x) >> 20); }

__device__ __forceinline__ void bsplit(float v, __nv_bfloat16& hi, __nv_bfloat16& lo) {
    hi = __float2bfloat16(v);
    lo = __float2bfloat16(v - __bfloat162float(hi));
}

// 16-byte async copy global -> shared (LDGSTS)
__device__ __forceinline__ void cp16(void* smem, const void* gmem) {
    unsigned sa = (unsigned)__cvta_generic_to_shared(smem);
    asm volatile("cp.async.cg.shared.global [%0], [%1], 16;" :: "r"(sa), "l"(gmem));
}
__device__ __forceinline__ void cp_commit() { asm volatile("cp.async.commit_group;"); }

// 4 radix-2 DIT stages (conj twiddles) on 16 register-resident points.
template<int SHIFT>
__device__ __forceinline__ void fft16_dit(float* vr_, float* vi_, int jbase, int stride) {
    #pragma unroll
    for (int ss = 0; ss < 4; ++ss) {
        int mloc = 1 << ss;
        #pragma unroll
        for (int u = 0; u < 8; ++u) {
            int t0 = ((u >> ss) << (ss + 1)) | (u & (mloc - 1));
            int t1 = t0 + mloc;
            int jg = jbase + stride * (u & (mloc - 1));
            float2 w = g_tw[jg << (SHIFT - ss)];
            float br = vr_[t1], bi = vi_[t1];
            float pr = br * w.x + bi * w.y;
            float pi = bi * w.x - br * w.y;
            float ar = vr_[t0], ai = vi_[t0];
            vr_[t0] = ar + pr;  vi_[t0] = ai + pi;
            vr_[t1] = ar - pr;  vi_[t1] = ai - pi;
        }
    }
}

// ---------------- twiddle table ----------------------------------------------------
__global__ void twiddle_kernel() {
    int k = blockIdx.x * blockDim.x + threadIdx.x;
    if (k < NH) {
        float s, c;
        sincospif(-(float)k / 4096.0f, &s, &c);
        g_tw[k] = make_float2(c, s);
    }
}

// ---------------- one-time bf16 hi/lo split of Wh ------------------------------------
__global__ void wsplit_kernel(const float* __restrict__ Wh_w) {
    int i = blockIdx.x * blockDim.x + threadIdx.x;
    if (i < HID * MSZ) bsplit(Wh_w[i], g_Whi[i], g_Wlo[i]);
}

// ---------------- u = relu(x @ Wu^T + b), fused x hi/lo split -------------------------
__global__ void u_kernel(const float* __restrict__ x,
                         const float* __restrict__ Wu_w,
                         const float* __restrict__ Wu_b) {
    int gw   = (blockIdx.x * blockDim.x + threadIdx.x) >> 5;
    int lane = threadIdx.x & 31;
    if (gw >= BATCH * SEQ) return;
    int b = gw >> 12, t = gw & (SEQ - 1);
    size_t rowoff = (size_t)(b * SEQ + t) * INPUT;
    const float* xp = x + rowoff;
    float a0 = 0.f, a1 = 0.f, a2 = 0.f, a3 = 0.f;
    #pragma unroll
    for (int i = lane; i < INPUT; i += 32) {
        float xv = xp[i];
        __nv_bfloat16 hi, lo;
        bsplit(xv, hi, lo);
        g_xhi[rowoff + i] = hi;
        g_xlo[rowoff + i] = lo;
        a0 = fmaf(xv, __ldg(&Wu_w[0 * INPUT + i]), a0);
        a1 = fmaf(xv, __ldg(&Wu_w[1 * INPUT + i]), a1);
        a2 = fmaf(xv, __ldg(&Wu_w[2 * INPUT + i]), a2);
        a3 = fmaf(xv, __ldg(&Wu_w[3 * INPUT + i]), a3);
    }
    #pragma unroll
    for (int off = 16; off; off >>= 1) {
        a0 += __shfl_down_sync(0xffffffffu, a0, off);
        a1 += __shfl_down_sync(0xffffffffu, a1, off);
        a2 += __shfl_down_sync(0xffffffffu, a2, off);
        a3 += __shfl_down_sync(0xffffffffu, a3, off);
    }
    if (lane == 0) {
        g_u[(b * 4 + 0) * SEQ + t] = fmaxf(a0 + Wu_b[0], 0.f);
        g_u[(b * 4 + 1) * SEQ + t] = fmaxf(a1 + Wu_b[1], 0.f);
        g_u[(b * 4 + 2) * SEQ + t] = fmaxf(a2 + Wu_b[2], 0.f);
        g_u[(b * 4 + 3) * SEQ + t] = fmaxf(a3 + Wu_b[3], 0.f);
    }
}

// ---------------- forward real FFT (radix-2^2 DIF, half spectrum, bitrev slots) ------
__global__ void fft_fwd_kernel(const float* __restrict__ Hin, int mode) {
    __shared__ float sre[NH];
    __shared__ float sim[NH];
    int row = blockIdx.x;
    int tid = threadIdx.x;
    const float* in = mode ? (Hin + (size_t)row * SEQ) : (g_u + (size_t)row * SEQ);

    const float2* in2 = (const float2*)in;
    #pragma unroll
    for (int r = 0; r < NH / FFT_T; ++r) {
        int n = tid + r * FFT_T;
        if (n < SEQ / 2) { float2 v = in2[n]; sre[n] = v.x; sim[n] = v.y; }
        else             { sre[n] = 0.f;      sim[n] = 0.f; }
    }
    __syncthreads();

    #pragma unroll
    for (int s = LOGH - 2; s >= 0; s -= 2) {
        int m = 1 << s;
        #pragma unroll
        for (int r = 0; r < (NH / 4) / FFT_T; ++r) {
            int k = tid + r * FFT_T;
            int j = k & (m - 1);
            int base = ((k >> s) << (s + 2)) + j;
            int ia = base, ib = base + m, ic = base + 2 * m, id = base + 3 * m;
            float2 w2 = g_tw[j << (LOGH - s - 1)];
            float2 w1 = g_tw[j << (LOGH - s)];
            float ar = sre[ia], ai = sim[ia];
            float br = sre[ib], bi = sim[ib];
            float cr = sre[ic], ci = sim[ic];
            float dr = sre[id], di = sim[id];
            float a1r = ar + cr, a1i = ai + ci;
            float tr  = ar - cr, ti  = ai - ci;
            float c1r = tr * w2.x - ti * w2.y;
            float c1i = tr * w2.y + ti * w2.x;
            float b1r = br + dr, b1i = bi + di;
            tr = br - dr; ti = bi - di;
            float er = tr * w2.x - ti * w2.y;
            float ei = tr * w2.y + ti * w2.x;
            float d1r = ei, d1i = -er;                     // * (-i)
            sre[ia] = a1r + b1r;  sim[ia] = a1i + b1i;
            tr = a1r - b1r; ti = a1i - b1i;
            sre[ib] = tr * w1.x - ti * w1.y;
            sim[ib] = tr * w1.y + ti * w1.x;
            sre[ic] = c1r + d1r;  sim[ic] = c1i + d1i;
            tr = c1r - d1r; ti = c1i - d1i;
            sre[id] = tr * w1.x - ti * w1.y;
            sim[id] = tr * w1.y + ti * w1.x;
        }
        __syncthreads();
    }

    if (mode == 0) {
        float* outre = g_Ure + (size_t)row * KS;
        float* outim = g_Uim + (size_t)row * KS;
        #pragma unroll
        for (int r = 0; r < NH / FFT_T; ++r) {
            int j = tid + r * FFT_T;
            if (j == 0) {
                float zr = sre[0], zi = sim[0];
                outre[0]  = zr + zi;  outim[0]  = 0.f;
                outre[NH] = zr - zi;  outim[NH] = 0.f;
            } else {
                int k = rev12(j);
                int p = rev12(NH - k);
                float zjr = sre[j], zji = sim[j];
                float zpr = sre[p], zpi = sim[p];
                float Ar = 0.5f * (zjr + zpr), Ai = 0.5f * (zji - zpi);
                float Br = 0.5f * (zji + zpi), Bi = -0.5f * (zjr - zpr);
                float2 w = g_tw[k];
                outre[j] = Ar + w.x * Br - w.y * Bi;
                outim[j] = Ai + w.x * Bi + w.y * Br;
            }
        }
    } else {
        size_t off = (size_t)row * KS;
        #pragma unroll
        for (int r = 0; r < NH / FFT_T; ++r) {
            int j = tid + r * FFT_T;
            float vre, vim;
            if (j == 0) {
                float zr = sre[0], zi = sim[0];
                vre = zr + zi; vim = 0.f;
                float nre = zr - zi;
                bsplit(nre, g_Hrehi[off + NH], g_Hrelo[off + NH]);
                bsplit(0.f, g_Himhi[off + NH], g_Himlo[off + NH]);
                for (int pcol = NH + 1; pcol < KS; ++pcol) {
                    g_Hrehi[off + pcol] = __float2bfloat16(0.f);
                    g_Hrelo[off + pcol] = __float2bfloat16(0.f);
                    g_Himhi[off + pcol] = __float2bfloat16(0.f);
                    g_Himlo[off + pcol] = __float2bfloat16(0.f);
                }
            } else {
                int k = rev12(j);
                int p = rev12(NH - k);
                float zjr = sre[j], zji = sim[j];
                float zpr = sre[p], zpi = sim[p];
                float Ar = 0.5f * (zjr + zpr), Ai = 0.5f * (zji - zpi);
                float Br = 0.5f * (zji + zpi), Bi = -0.5f * (zjr - zpr);
                float2 w = g_tw[k];
                vre = Ar + w.x * Br - w.y * Bi;
                vim = Ai + w.x * Bi + w.y * Br;
            }
            bsplit(vre, g_Hrehi[off + j], g_Hrelo[off + j]);
            bsplit(vim, g_Himhi[off + j], g_Himlo[off + j]);
        }
    }
}

// ---------------- G build: cp.async double-buffered bf16-split GEMM ------------------
struct GBuf {
    __nv_bfloat16 Ahi[64][40], Alo[64][40];          // [m][k]
    __nv_bfloat16 Bhi[2][32][136], Blo[2][32][136];  // [re/im][k][n]
};
#define GB_SMEM ((int)(2 * sizeof(GBuf)))

__device__ __forceinline__ void gbuild_load(GBuf& bb, int d, int h0, int k0, int o0, int tid) {
    {
        int m = tid >> 2, c = (tid & 3) * 8;
        size_t src = (size_t)(h0 + m) * MSZ + d * ORDER + o0 + c;
        cp16(&bb.Ahi[m][c], &g_Whi[src]);
        cp16(&bb.Alo[m][c], &g_Wlo[src]);
    }
    #pragma unroll
    for (int r = 0; r < 2; ++r) {
        int oo = (tid >> 4) + r * 16;
        int c  = (tid & 15) * 8;
        size_t src = (size_t)(o0 + oo) * KS + k0 + c;
        cp16(&bb.Bhi[0][oo][c], &g_Hrehi[src]);
        cp16(&bb.Blo[0][oo][c], &g_Hrelo[src]);
        cp16(&bb.Bhi[1][oo][c], &g_Himhi[src]);
        cp16(&bb.Blo[1][oo][c], &g_Himlo[src]);
    }
}

__global__ __launch_bounds__(256)
void gbuild_bf16_kernel() {
    extern __shared__ char smem_raw[];
    GBuf* bufs = (GBuf*)smem_raw;
    int d  = blockIdx.z;
    int h0 = blockIdx.y * 64;
    int k0 = blockIdx.x * 128;
    int tid = threadIdx.x;
    int w  = tid >> 5;
    int wm = w & 1;
    int wn = w >> 1;

    FC accr[2][2], acci[2][2];
    #pragma unroll
    for (int m2 = 0; m2 < 2; ++m2)
        #pragma unroll
        for (int n2 = 0; n2 < 2; ++n2) {
            wmma::fill_fragment(accr[m2][n2], 0.f);
            wmma::fill_fragment(acci[m2][n2], 0.f);
        }

    gbuild_load(bufs[0], d, h0, k0, 0, tid);
    cp_commit();

    #pragma unroll
    for (int it = 0; it < ORDER / 32; ++it) {
        int cur = it & 1;
        if (it + 1 < ORDER / 32) {
            gbuild_load(bufs[cur ^ 1], d, h0, k0, (it + 1) * 32, tid);
            cp_commit();
            asm volatile("cp.async.wait_group 1;");
        } else {
            asm volatile("cp.async.wait_group 0;");
        }
        __syncthreads();
        GBuf& bb = bufs[cur];
        #pragma unroll
        for (int kk = 0; kk < 32; kk += 16) {
            FA ahi[2], alo[2];
            #pragma unroll
            for (int m2 = 0; m2 < 2; ++m2) {
                wmma::load_matrix_sync(ahi[m2], &bb.Ahi[wm * 32 + m2 * 16][kk], 40);
                wmma::load_matrix_sync(alo[m2], &bb.Alo[wm * 32 + m2 * 16][kk], 40);
            }
            #pragma unroll
            for (int n2 = 0; n2 < 2; ++n2) {
                FBr bhi, blo;
                wmma::load_matrix_sync(bhi, &bb.Bhi[0][kk][wn * 32 + n2 * 16], 136);
                wmma::load_matrix_sync(blo, &bb.Blo[0][kk][wn * 32 + n2 * 16], 136);
                #pragma unroll
                for (int m2 = 0; m2 < 2; ++m2) {
                    wmma::mma_sync(accr[m2][n2], ahi[m2], bhi, accr[m2][n2]);
                    wmma::mma_sync(accr[m2][n2], alo[m2], bhi, accr[m2][n2]);
                    wmma::mma_sync(accr[m2][n2], ahi[m2], blo, accr[m2][n2]);
                }
                wmma::load_matrix_sync(bhi, &bb.Bhi[1][kk][wn * 32 + n2 * 16], 136);
                wmma::load_matrix_sync(blo, &bb.Blo[1][kk][wn * 32 + n2 * 16], 136);
                #pragma unroll
                for (int m2 = 0; m2 < 2; ++m2) {
                    wmma::mma_sync(acci[m2][n2], ahi[m2], bhi, acci[m2][n2]);
                    wmma::mma_sync(acci[m2][n2], alo[m2], bhi, acci[m2][n2]);
                    wmma::mma_sync(acci[m2][n2], ahi[m2], blo, acci[m2][n2]);
                }
            }
        }
        __syncthreads();
    }
    #pragma unroll
    for (int m2 = 0; m2 < 2; ++m2)
        #pragma unroll
        for (int n2 = 0; n2 < 2; ++n2) {
            size_t dst = ((size_t)(h0 + wm * 32 + m2 * 16) * MD + d) * KS
                       + k0 + wn * 32 + n2 * 16;
            wmma::store_matrix_sync(&g_Gre[dst], accr[m2][n2], MD * KS, wmma::mem_row_major);
            wmma::store_matrix_sync(&g_Gim[dst], acci[m2][n2], MD * KS, wmma::mem_row_major);
        }
}

// ---------------- hx GEMM: cp.async double-buffered, 32x32 warp tiles ----------------
struct HBuf {
    __nv_bfloat16 Ahi[64][40], Alo[64][40];    // [h][i]
    __nv_bfloat16 Bhi[128][40], Blo[128][40];  // [t][i]
};
#define HX_SMEM ((int)(2 * sizeof(HBuf)))

__device__ __forceinline__ void hx_load(HBuf& bb, int b, int h0, int t0, int i0, int tid) {
    {
        int m = tid >> 2, c = (tid & 3) * 8;
        size_t src = (size_t)(h0 + m) * MSZ + MD * ORDER + i0 + c;
        cp16(&bb.Ahi[m][c], &g_Whi[src]);
        cp16(&bb.Alo[m][c], &g_Wlo[src]);
    }
    #pragma unroll
    for (int r = 0; r < 2; ++r) {
        int e = tid + r * 256;
        int tt = e >> 2, c = (e & 3) * 8;
        size_t src = (size_t)(b * SEQ + t0 + tt) * INPUT + i0 + c;
        cp16(&bb.Bhi[tt][c], &g_xhi[src]);
        cp16(&bb.Blo[tt][c], &g_xlo[src]);
    }
}

__global__ __launch_bounds__(256)
void hx_bf16_kernel(const float* __restrict__ Wh_b) {
    extern __shared__ char smem_raw[];
    HBuf* bufs = (HBuf*)smem_raw;
    __shared__ float sBias[64][16];
    int b  = blockIdx.z;
    int h0 = blockIdx.y * 64;
    int t0 = blockIdx.x * 128;
    int tid = threadIdx.x;
    int w  = tid >> 5;
    int wm = w & 1;      // 2 m-tiles of 32
    int wn = w >> 1;     // 4 n-tiles of 32

    #pragma unroll
    for (int r = 0; r < 4; ++r) {
        int e = tid + r * 256;
        sBias[e >> 4][e & 15] = Wh_b[h0 + (e >> 4)];
    }

    hx_load(bufs[0], b, h0, t0, 0, tid);
    cp_commit();
    __syncthreads();   // sBias ready

    FC acc[2][2];
    #pragma unroll
    for (int m2 = 0; m2 < 2; ++m2)
        #pragma unroll
        for (int n2 = 0; n2 < 2; ++n2)
            wmma::load_matrix_sync(acc[m2][n2], &sBias[wm * 32 + m2 * 16][0], 16,
                                   wmma::mem_row_major);

    #pragma unroll
    for (int it = 0; it < INPUT / 32; ++it) {
        int cur = it & 1;
        if (it + 1 < INPUT / 32) {
            hx_load(bufs[cur ^ 1], b, h0, t0, (it + 1) * 32, tid);
            cp_commit();
            asm volatile("cp.async.wait_group 1;");
        } else {
            asm volatile("cp.async.wait_group 0;");
        }
        __syncthreads();
        HBuf& bb = bufs[cur];
        #pragma unroll
        for (int kk = 0; kk < 32; kk += 16) {
            FA ahi[2], alo[2];
            #pragma unroll
            for (int m2 = 0; m2 < 2; ++m2) {
                wmma::load_matrix_sync(ahi[m2], &bb.Ahi[wm * 32 + m2 * 16][kk], 40);
                wmma::load_matrix_sync(alo[m2], &bb.Alo[wm * 32 + m2 * 16][kk], 40);
            }
            #pragma unroll
            for (int n2 = 0; n2 < 2; ++n2) {
                FBc bhi, blo;
                wmma::load_matrix_sync(bhi, &bb.Bhi[wn * 32 + n2 * 16][kk], 40);
                wmma::load_matrix_sync(blo, &bb.Blo[wn * 32 + n2 * 16][kk], 40);
                #pragma unroll
                for (int m2 = 0; m2 < 2; ++m2) {
                    wmma::mma_sync(acc[m2][n2], ahi[m2], bhi, acc[m2][n2]);
                    wmma::mma_sync(acc[m2][n2], alo[m2], bhi, acc[m2][n2]);
                    wmma::mma_sync(acc[m2][n2], ahi[m2], blo, acc[m2][n2]);
                }
            }
        }
        __syncthreads();
    }
    #pragma unroll
    for (int m2 = 0; m2 < 2; ++m2)
        #pragma unroll
        for (int n2 = 0; n2 < 2; ++n2) {
            size_t dst = ((size_t)b * HID + h0 + wm * 32 + m2 * 16) * SEQ
                       + t0 + wn * 32 + n2 * 16;
            wmma::store_matrix_sync(&g_hx[dst], acc[m2][n2], SEQ, wmma::mem_row_major);
        }
}

// ---------------- P = sum_d G*U ; real-iFFT (3x radix-16 reg passes, 2 batches) ------
__global__ __launch_bounds__(FFT_T, 2)
void pifft_kernel() {
    __shared__ float sre[2][SMSZ];
    __shared__ float sim[2][SMSZ];
    __shared__ float s_nyq[2];
    int h  = blockIdx.x >> 2;
    int bp = blockIdx.x & 3;
    int b0 = bp * 2;
    int tid = threadIdx.x;

    const float* Ur0 = g_Ure + (size_t)b0 * MD * KS;
    const float* Ui0 = g_Uim + (size_t)b0 * MD * KS;
    const float* Ur1 = Ur0 + MD * KS;
    const float* Ui1 = Ui0 + MD * KS;
    const float* Gr  = g_Gre + (size_t)h * MD * KS;
    const float* Gi  = g_Gim + (size_t)h * MD * KS;

    #pragma unroll
    for (int r = 0; r < NH / FFT_T; ++r) {
        int j = tid + r * FFT_T;
        float pr0 = 0.f, pi0 = 0.f, pr1 = 0.f, pi1 = 0.f;
        #pragma unroll
        for (int d = 0; d < MD; ++d) {
            float gr = Gr[d * KS + j], gi = Gi[d * KS + j];
            float ur = Ur0[d * KS + j], ui = Ui0[d * KS + j];
            pr0 += ur * gr - ui * gi;
            pi0 += ur * gi + ui * gr;
            ur = Ur1[d * KS + j]; ui = Ui1[d * KS + j];
            pr1 += ur * gr - ui * gi;
            pi1 += ur * gi + ui * gr;
        }
        int pj = PH(j);
        sre[0][pj] = pr0; sim[0][pj] = pi0;
        sre[1][pj] = pr1; sim[1][pj] = pi1;
    }
    if (tid < 2) {
        const float* Urb = tid ? Ur1 : Ur0;
        const float* Uib = tid ? Ui1 : Ui0;
        float pn = 0.f;
        #pragma unroll
        for (int d = 0; d < MD; ++d)
            pn += Urb[d * KS + NH] * Gr[d * KS + NH] - Uib[d * KS + NH] * Gi[d * KS + NH];
        s_nyq[tid] = pn;
    }
    __syncthreads();

    float zr[2][NH / FFT_T], zi[2][NH / FFT_T];
    #pragma unroll
    for (int r = 0; r < NH / FFT_T; ++r) {
        int j = tid + r * FFT_T;
        if (j == 0) {
            #pragma unroll
            for (int q = 0; q < 2; ++q) {
                float p0 = sre[q][PH(0)], pn = s_nyq[q];
                zr[q][r] = 0.5f * (p0 + pn);
                zi[q][r] = 0.5f * (p0 - pn);
            }
        } else {
            int k = rev12(j);
            int p = rev12(NH - k);
            int pj = PH(j), pp = PH(p);
            float2 w = g_tw[k];
            #pragma unroll
            for (int q = 0; q < 2; ++q) {
                float pjr = sre[q][pj], pji = sim[q][pj];
                float ppr = sre[q][pp], ppi = sim[q][pp];
                float Xer = 0.5f * (pjr + ppr), Xei = 0.5f * (pji - ppi);
                float Dr  = 0.5f * (pjr - ppr), Di  = 0.5f * (pji + ppi);
                float Xor = w.x * Dr + w.y * Di;
                float Xoi = w.x * Di - w.y * Dr;
                zr[q][r] = Xer - Xoi;
                zi[q][r] = Xei + Xor;
            }
        }
    }
    __syncthreads();
    #pragma unroll
    for (int r = 0; r < NH / FFT_T; ++r) {
        int pj = PH(tid + r * FFT_T);
        sre[0][pj] = zr[0][r]; sim[0][pj] = zi[0][r];
        sre[1][pj] = zr[1][r]; sim[1][pj] = zi[1][r];
    }
    __syncthreads();

    {
        int q = tid >> 8;
        int g = tid & 255;
        float* qre = sre[q];
        float* qim = sim[q];
        float vr_[16], vi_[16];
        {
            int pb = PH(g << 4);
            #pragma unroll
            for (int t = 0; t < 16; ++t) { vr_[t] = qre[pb + t]; vi_[t] = qim[pb + t]; }
            fft16_dit<12>(vr_, vi_, 0, 1);
            #pragma unroll
            for (int t = 0; t < 16; ++t) { qre[pb + t] = vr_[t]; qim[pb + t] = vi_[t]; }
        }
        __syncthreads();
        {
            int base = ((g >> 4) << 8) + (g & 15);
            #pragma unroll
            for (int t = 0; t < 16; ++t) {
                int p = PH(base + (t << 4));
                vr_[t] = qre[p]; vi_[t] = qim[p];
            }
            fft16_dit<8>(vr_, vi_, g & 15, 16);
            #pragma unroll
            for (int t = 0; t < 16; ++t) {
                int p = PH(base + (t << 4));
                qre[p] = vr_[t]; qim[p] = vi_[t];
            }
        }
        __syncthreads();
        {
            #pragma unroll
            for (int t = 0; t < 16; ++t) {
                int p = PH(g + (t << 8));
                vr_[t] = qre[p]; vi_[t] = qim[p];
            }
            fft16_dit<4>(vr_, vi_, g, 256);
            #pragma unroll
            for (int t = 0; t < 16; ++t) {
                int p = PH(g + (t << 8));
                qre[p] = vr_[t]; qim[p] = vi_[t];
            }
        }
    }
    __syncthreads();

    const float inv_n = 1.0f / 4096.0f;
    #pragma unroll
    for (int q = 0; q < 2; ++q) {
        float2* hx2 = (float2*)(g_hx + (size_t)((b0 + q) * HID + h) * SEQ);
        #pragma unroll
        for (int r = 0; r < (SEQ / 2) / FFT_T; ++r) {
            int n = tid + r * FFT_T;
            int pn = PH(n);
            float2 old = hx2[n];
            float2 v;
            v.x = fmaxf(fmaf(sre[q][pn], inv_n, old.x), 0.f);
            v.y = fmaxf(fmaf(sim[q][pn], inv_n, old.y), 0.f);
            hx2[n] = v;
        }
    }
}

// ---------------- transpose [b][h][t] -> out [b][t][h] -------------------------------
__global__ void fuse_kernel(float* __restrict__ out) {
    __shared__ float tile[32][33];
    int b  = blockIdx.z;
    int h0 = blockIdx.y * 32;
    int t0 = blockIdx.x * 32;
    int tx = threadIdx.x, ty = threadIdx.y;
    #pragma unroll
    for (int r = 0; r < 32; r += 8)
        tile[ty + r][tx] = g_hx[(size_t)(b * HID + h0 + ty + r) * SEQ + t0 + tx];
    __syncthreads();
    #pragma unroll
    for (int r = 0; r < 32; r += 8)
        out[(size_t)(b * SEQ + t0 + ty + r) * HID + h0 + tx] = tile[tx][ty + r];
}

// ---------------- h[:, -1, :] appended after h ----------------------------------------
__global__ void last_kernel(float* __restrict__ out) {
    int i = blockIdx.x * blockDim.x + threadIdx.x;
    if (i < BATCH * HID)
        out[(size_t)BATCH * SEQ * HID + i] = g_hx[(size_t)i * SEQ + (SEQ - 1)];
}

// ---------------- launch ---------------------------------------------------------------
extern "C" void kernel_launch(void* const* d_in, const int* in_sizes, int n_in,
                              void* d_out, int out_size) {
    const float* x    = (const float*)d_in[0];
    const float* Wu_w = (const float*)d_in[1];
    const float* Wu_b = (const float*)d_in[2];
    const float* Wh_w = (const float*)d_in[3];
    const float* Wh_b = (const float*)d_in[4];
    const float* H    = (const float*)d_in[5];
    float* out = (float*)d_out;

    static int configured = 0;
    if (!configured) {
        cudaFuncSetAttribute(gbuild_bf16_kernel,
                             cudaFuncAttributeMaxDynamicSharedMemorySize, GB_SMEM);
        cudaFuncSetAttribute(hx_bf16_kernel,
                             cudaFuncAttributeMaxDynamicSharedMemorySize, HX_SMEM);
        configured = 1;
    }

    twiddle_kernel<<<8, 512>>>();
    wsplit_kernel<<<(HID * MSZ + 511) / 512, 512>>>(Wh_w);
    u_kernel<<<(BATCH * SEQ * 32) / 256, 256>>>(x, Wu_w, Wu_b);

    fft_fwd_kernel<<<32,    FFT_T>>>(nullptr, 0);   // u spectra (fp32)
    fft_fwd_kernel<<<ORDER, FFT_T>>>(H, 1);         // H spectra (bf16 hi/lo)

    gbuild_bf16_kernel<<<dim3(KS / 128, HID / 64, MD), 256, GB_SMEM>>>();
    hx_bf16_kernel<<<dim3(SEQ / 128, HID / 64, BATCH), 256, HX_SMEM>>>(Wh_b);

    pifft_kernel<<<HID * BATCH / 2, FFT_T>>>();

    fuse_kernel<<<dim3(SEQ / 32, HID / 32, BATCH), dim3(32, 8)>>>(out);
    if (out_size >= BATCH * SEQ * HID + BATCH * HID)
        last_kernel<<<8, 512>>>(out);
}